// round 13
// baseline (speedup 1.0000x reference)
#include <cuda_runtime.h>
#include <cuda_bf16.h>
#include <cuda_fp16.h>
#include <cstdint>
#include <cstddef>

// ---------------------------------------------------------------------------
// Problem constants
// ---------------------------------------------------------------------------
static const int NPTS  = 65536;
static const int HID   = 512;
static const int HH    = 1024;
static const int KVSPL = 16;

// ---------------------------------------------------------------------------
// Scratch (device globals; no allocation allowed)
// ---------------------------------------------------------------------------
__device__ float g_qk  [65536u * 1024u];      // K, later Q
__device__ float g_v   [65536u * 1024u];      // V; head-0 half later holds attn
__device__ float g_h   [65536u * 512u];       // fc0 output
__device__ float g_kvp [32u * 512u * 512u];   // split-K partials
__device__ float g_kvs [2u * 512u * 512u];    // K^T V per head [m][d]
__device__ float g_kvsT[2u * 512u * 512u];    // transposed [d][m], scaled 2^-8
__device__ float g_wt  [8u * 524288u];        // transposed weights (slots)
__device__ float g_ksp [512u * 1024u];
__device__ float g_ks  [1024u];
__device__ float g_red [8192u];
__device__ float g_scal[2u];
__device__ float g_qdp [4u * 65536u];
__device__ float g_inv [2u * 65536u];

// ---------------------------------------------------------------------------
// Helpers
// ---------------------------------------------------------------------------
__device__ __forceinline__ unsigned tf32_of(float f) {
    unsigned u;
    asm("cvt.rna.tf32.f32 %0, %1;" : "=r"(u) : "f"(f));
    return u;
}

// pack two floats into f16x2 (lo = first arg)
__device__ __forceinline__ unsigned h2pack(float lo, float hi) {
    unsigned u;
    asm("{ .reg .f16 l, h; cvt.rn.f16.f32 l, %1; cvt.rn.f16.f32 h, %2; "
        "mov.b32 %0, {l, h}; }" : "=r"(u) : "f"(lo), "f"(hi));
    return u;
}

__device__ __forceinline__ void mma_tf32(float c[4], const unsigned a[4],
                                         const unsigned b[2]) {
    asm volatile(
        "mma.sync.aligned.m16n8k8.row.col.f32.tf32.tf32.f32 "
        "{%0,%1,%2,%3},{%4,%5,%6,%7},{%8,%9},{%0,%1,%2,%3};\n"
        : "+f"(c[0]), "+f"(c[1]), "+f"(c[2]), "+f"(c[3])
        : "r"(a[0]), "r"(a[1]), "r"(a[2]), "r"(a[3]), "r"(b[0]), "r"(b[1]));
}

__device__ __forceinline__ void mma_f16(float c[4], const unsigned a[4],
                                        const unsigned b[2]) {
    asm volatile(
        "mma.sync.aligned.m16n8k16.row.col.f32.f16.f16.f32 "
        "{%0,%1,%2,%3},{%4,%5,%6,%7},{%8,%9},{%0,%1,%2,%3};\n"
        : "+f"(c[0]), "+f"(c[1]), "+f"(c[2]), "+f"(c[3])
        : "r"(a[0]), "r"(a[1]), "r"(a[2]), "r"(a[3]), "r"(b[0]), "r"(b[1]));
}

__device__ __forceinline__ float block_reduce_sum(float v, float* sm) {
    int tid = threadIdx.x;
    int lane = tid & 31, wid = tid >> 5;
    #pragma unroll
    for (int o = 16; o > 0; o >>= 1) v += __shfl_down_sync(0xffffffffu, v, o);
    __syncthreads();
    if (lane == 0) sm[wid] = v;
    __syncthreads();
    if (tid == 0) {
        float s = 0.f;
        #pragma unroll
        for (int i = 0; i < 8; i++) s += sm[i];
        sm[0] = s;
    }
    __syncthreads();
    return sm[0];
}

// ---------------------------------------------------------------------------
// Tiled transpose with scale: out[C][R] = scale * in[R][C]^T
// block (32,8), grid (C/32, R/32)
// ---------------------------------------------------------------------------
__global__ void transpose_k(const float* __restrict__ in, int R, int C,
                            float* __restrict__ out, float scale)
{
    __shared__ float t[32][33];
    int c0 = blockIdx.x * 32, r0 = blockIdx.y * 32;
    int x = threadIdx.x, y = threadIdx.y;
    #pragma unroll
    for (int i = 0; i < 32; i += 8)
        t[y + i][x] = in[(size_t)(r0 + y + i) * C + c0 + x];
    __syncthreads();
    #pragma unroll
    for (int i = 0; i < 32; i += 8)
        out[(size_t)(c0 + y + i) * R + r0 + x] = t[x][y + i] * scale;
}

// ===========================================================================
// FP16 GEMM core: block tile 128(M) x 256(N), BK=32, 256 threads.
// 8 warps 2(M) x 4(N); warp tile 64x64 -> 4x8 m16n8k16 fragments (fp32 accum).
// A [M,*] row-major fp32 (lda); BT [Ntot][512] row-major fp32 (K-major).
// Fused epilogue options: ss / colsum / q.ks row-dot (as round-9 v2).
// ===========================================================================
__global__ __launch_bounds__(256) void gemm_h_nn(
    const float* __restrict__ A, const float* __restrict__ BT,
    const float* __restrict__ bias, float* __restrict__ C,
    int K, int lda, int ldc,
    float* __restrict__ ss_out,
    float* __restrict__ colsum_out,
    const float* __restrict__ ksvec,
    float* __restrict__ qdp_out)
{
    __shared__ unsigned As[128 * 20];   // [m][k2] half2, stride 20 (16 used)
    __shared__ unsigned Bs[256 * 20];   // [n][k2] half2
    __shared__ float epism[4096];
    __shared__ float rsm[8];

    const int tid = threadIdx.x;
    const int lane = tid & 31;
    const int wid = tid >> 5;
    const int gid = lane >> 2, tig = lane & 3;
    const int warp_m = (wid & 1) * 64;
    const int warp_n = (wid >> 1) * 64;
    const int m0 = blockIdx.y * 128;
    const int n0 = blockIdx.x * 256;
    const int T = K >> 5;

    float acc[4][8][4];
    #pragma unroll
    for (int i = 0; i < 4; i++)
        #pragma unroll
        for (int j = 0; j < 8; j++)
            #pragma unroll
            for (int r = 0; r < 4; r++) acc[i][j][r] = 0.f;

    for (int t = 0; t < T; t++) {
        const int k0 = t * 32;
        #pragma unroll
        for (int it = 0; it < 4; it++) {
            int idx = tid + it * 256;
            int r = idx >> 3, c = idx & 7;
            float4 a4 = *(const float4*)(A + (size_t)(m0 + r) * lda + k0 + c * 4);
            uint2 u;
            u.x = h2pack(a4.x, a4.y);
            u.y = h2pack(a4.z, a4.w);
            *(uint2*)&As[r * 20 + c * 2] = u;
        }
        #pragma unroll
        for (int it = 0; it < 8; it++) {
            int idx = tid + it * 256;
            int r = idx >> 3, c = idx & 7;
            float4 b4 = *(const float4*)(BT + (size_t)(n0 + r) * 512 + k0 + c * 4);
            uint2 u;
            u.x = h2pack(b4.x, b4.y);
            u.y = h2pack(b4.z, b4.w);
            *(uint2*)&Bs[r * 20 + c * 2] = u;
        }
        __syncthreads();

        #pragma unroll
        for (int kk2 = 0; kk2 < 16; kk2 += 8) {
            unsigned afr[4][4], bfr[8][2];
            #pragma unroll
            for (int i = 0; i < 4; i++) {
                int mm = warp_m + i * 16 + gid;
                afr[i][0] = As[mm * 20 + kk2 + tig];
                afr[i][1] = As[(mm + 8) * 20 + kk2 + tig];
                afr[i][2] = As[mm * 20 + kk2 + tig + 4];
                afr[i][3] = As[(mm + 8) * 20 + kk2 + tig + 4];
            }
            #pragma unroll
            for (int j = 0; j < 8; j++) {
                int nn = warp_n + j * 8 + gid;
                bfr[j][0] = Bs[nn * 20 + kk2 + tig];
                bfr[j][1] = Bs[nn * 20 + kk2 + tig + 4];
            }
            #pragma unroll
            for (int i = 0; i < 4; i++)
                #pragma unroll
                for (int j = 0; j < 8; j++) mma_f16(acc[i][j], afr[i], bfr[j]);
        }
        __syncthreads();
    }

    // ---- epilogue: bias add, store, fused reductions ----
    const bool do_cs = (colsum_out != nullptr);
    const bool do_qd = (qdp_out != nullptr);
    float ss = 0.f;
    float qd[4][2];
    #pragma unroll
    for (int i = 0; i < 4; i++) { qd[i][0] = 0.f; qd[i][1] = 0.f; }

    #pragma unroll
    for (int j = 0; j < 8; j++) {
        int c = n0 + warp_n + j * 8 + tig * 2;
        float bx = bias ? bias[c] : 0.f;
        float by = bias ? bias[c + 1] : 0.f;
        float ks0 = 0.f, ks1 = 0.f;
        if (do_qd) { ks0 = ksvec[c]; ks1 = ksvec[c + 1]; }
        float cs0 = 0.f, cs1 = 0.f;
        #pragma unroll
        for (int i = 0; i < 4; i++) {
            int r = m0 + warp_m + i * 16 + gid;
            float x0 = acc[i][j][0] + bx, x1 = acc[i][j][1] + by;
            float x2 = acc[i][j][2] + bx, x3 = acc[i][j][3] + by;
            *(float2*)(C + (size_t)r * ldc + c)       = make_float2(x0, x1);
            *(float2*)(C + (size_t)(r + 8) * ldc + c) = make_float2(x2, x3);
            ss += x0 * x0 + x1 * x1 + x2 * x2 + x3 * x3;
            cs0 += x0 + x2; cs1 += x1 + x3;
            qd[i][0] += x0 * ks0 + x1 * ks1;
            qd[i][1] += x2 * ks0 + x3 * ks1;
        }
        if (do_cs) {
            epism[(tid * 8 + j) * 2 + 0] = cs0;
            epism[(tid * 8 + j) * 2 + 1] = cs1;
        }
    }

    if (do_cs) {
        __syncthreads();
        int c = tid;
        int wn = c >> 6, j = (c >> 3) & 7, tg = (c & 7) >> 1, e = c & 1;
        float s = 0.f;
        #pragma unroll
        for (int wm = 0; wm < 2; wm++)
            #pragma unroll
            for (int g = 0; g < 8; g++) {
                int t2 = (2 * wn + wm) * 32 + g * 4 + tg;
                s += epism[(t2 * 8 + j) * 2 + e];
            }
        colsum_out[(size_t)blockIdx.y * 1024 + n0 + c] = s;
    }

    if (do_qd) {
        __syncthreads();
        #pragma unroll
        for (int i = 0; i < 4; i++) {
            epism[(tid * 4 + i) * 2 + 0] = qd[i][0];
            epism[(tid * 4 + i) * 2 + 1] = qd[i][1];
        }
        __syncthreads();
        if (tid < 128) {
            int rl = tid;
            int wm = rl >> 6, rem = rl & 63;
            int i = rem >> 4, hf = (rem >> 3) & 1, g = rem & 7;
            float s = 0.f;
            #pragma unroll
            for (int wn = 0; wn < 4; wn++)
                #pragma unroll
                for (int tg = 0; tg < 4; tg++) {
                    int t2 = (2 * wn + wm) * 32 + g * 4 + tg;
                    s += epism[(t2 * 4 + i) * 2 + hf];
                }
            qdp_out[(size_t)blockIdx.x * 65536u + m0 + rl] = s;
        }
    }

    if (ss_out) {
        float s = block_reduce_sum(ss, rsm);
        if (tid == 0) ss_out[blockIdx.y * gridDim.x + blockIdx.x] = s;
    }
}

// ---------------------------------------------------------------------------
// FP16 fused attention GEMM:
//   C[r,c] (+)= 0.5 * inv[r] * ( (A@B)[r,c] * (s*256)  +  65536 * V[r,c] )
// BT = kvsT pre-scaled by 2^-8 (fp16 range guard); 2^8 folded into s here.
// A = q head slice (lda 1024); grid (2, 512), N=512.
// ---------------------------------------------------------------------------
__global__ __launch_bounds__(256) void gemm_h_attn(
    const float* __restrict__ A, const float* __restrict__ BT,
    const float* __restrict__ Vb, const float* __restrict__ invp,
    const float* __restrict__ scal, float* __restrict__ C, int beta)
{
    __shared__ unsigned As[128 * 20];
    __shared__ unsigned Bs[256 * 20];

    const int tid = threadIdx.x;
    const int lane = tid & 31;
    const int wid = tid >> 5;
    const int gid = lane >> 2, tig = lane & 3;
    const int warp_m = (wid & 1) * 64;
    const int warp_n = (wid >> 1) * 64;
    const int m0 = blockIdx.y * 128;
    const int n0 = blockIdx.x * 256;

    float acc[4][8][4];
    #pragma unroll
    for (int i = 0; i < 4; i++)
        #pragma unroll
        for (int j = 0; j < 8; j++)
            #pragma unroll
            for (int r = 0; r < 4; r++) acc[i][j][r] = 0.f;

    for (int t = 0; t < 16; t++) {
        const int k0 = t * 32;
        #pragma unroll
        for (int it = 0; it < 4; it++) {
            int idx = tid + it * 256;
            int r = idx >> 3, c = idx & 7;
            float4 a4 = *(const float4*)(A + (size_t)(m0 + r) * 1024 + k0 + c * 4);
            uint2 u;
            u.x = h2pack(a4.x, a4.y);
            u.y = h2pack(a4.z, a4.w);
            *(uint2*)&As[r * 20 + c * 2] = u;
        }
        #pragma unroll
        for (int it = 0; it < 8; it++) {
            int idx = tid + it * 256;
            int r = idx >> 3, c = idx & 7;
            float4 b4 = *(const float4*)(BT + (size_t)(n0 + r) * 512 + k0 + c * 4);
            uint2 u;
            u.x = h2pack(b4.x, b4.y);
            u.y = h2pack(b4.z, b4.w);
            *(uint2*)&Bs[r * 20 + c * 2] = u;
        }
        __syncthreads();

        #pragma unroll
        for (int kk2 = 0; kk2 < 16; kk2 += 8) {
            unsigned afr[4][4], bfr[8][2];
            #pragma unroll
            for (int i = 0; i < 4; i++) {
                int mm = warp_m + i * 16 + gid;
                afr[i][0] = As[mm * 20 + kk2 + tig];
                afr[i][1] = As[(mm + 8) * 20 + kk2 + tig];
                afr[i][2] = As[mm * 20 + kk2 + tig + 4];
                afr[i][3] = As[(mm + 8) * 20 + kk2 + tig + 4];
            }
            #pragma unroll
            for (int j = 0; j < 8; j++) {
                int nn = warp_n + j * 8 + gid;
                bfr[j][0] = Bs[nn * 20 + kk2 + tig];
                bfr[j][1] = Bs[nn * 20 + kk2 + tig + 4];
            }
            #pragma unroll
            for (int i = 0; i < 4; i++)
                #pragma unroll
                for (int j = 0; j < 8; j++) mma_f16(acc[i][j], afr[i], bfr[j]);
        }
        __syncthreads();
    }

    // 2^8 compensates the 2^-8 pre-scale on kvsT (exact power-of-two)
    const float s = rsqrtf(scal[0] * scal[1]) * 256.0f;
    #pragma unroll
    for (int j = 0; j < 8; j++) {
        int c = n0 + warp_n + j * 8 + tig * 2;
        #pragma unroll
        for (int i = 0; i < 4; i++) {
            int r = m0 + warp_m + i * 16 + gid;
            float iv0 = invp[2 * (size_t)r];
            float iv1 = invp[2 * (size_t)(r + 8)];
            float2 va  = *(const float2*)(Vb + (size_t)r * 1024 + c);
            float2 vbv = *(const float2*)(Vb + (size_t)(r + 8) * 1024 + c);
            float x0 = (acc[i][j][0] * s + 65536.f * va.x)  * iv0 * 0.5f;
            float x1 = (acc[i][j][1] * s + 65536.f * va.y)  * iv0 * 0.5f;
            float x2 = (acc[i][j][2] * s + 65536.f * vbv.x) * iv1 * 0.5f;
            float x3 = (acc[i][j][3] * s + 65536.f * vbv.y) * iv1 * 0.5f;
            float* c0 = C + (size_t)r * 1024 + c;
            float* c1 = C + (size_t)(r + 8) * 1024 + c;
            if (beta) {
                float2 o0 = *(float2*)c0, o1 = *(float2*)c1;
                x0 += o0.x; x1 += o0.y; x2 += o1.x; x3 += o1.y;
            }
            *(float2*)c0 = make_float2(x0, x1);
            *(float2*)c1 = make_float2(x2, x3);
        }
    }
}

// ---------------------------------------------------------------------------
// TN GEMM for kvs (tf32 v2, known-good): C[m,d] = sum_l K[l,m]*V[l,d], split-K
// ---------------------------------------------------------------------------
__global__ __launch_bounds__(256) void gemm_tn_kv_v2(
    const float* __restrict__ Kp, const float* __restrict__ Vp,
    float* __restrict__ part)
{
    __shared__ unsigned As[16][264];
    __shared__ unsigned Bs[16][264];

    const int tid = threadIdx.x;
    const int lane = tid & 31;
    const int wid = tid >> 5;
    const int gid = lane >> 2, tig = lane & 3;
    const int warp_m = (wid & 1) * 64;
    const int warp_n = (wid >> 1) * 64;
    const int d0 = blockIdx.x * 256;
    const int m0 = blockIdx.y * 128;
    const int h  = blockIdx.z >> 4;
    const int sp = blockIdx.z & 15;
    const int CH = NPTS / KVSPL;

    const float* Ab = Kp + (size_t)h * 512;
    const float* Bb = Vp + (size_t)h * 512;

    float acc[4][8][4];
    #pragma unroll
    for (int i = 0; i < 4; i++)
        #pragma unroll
        for (int j = 0; j < 8; j++)
            #pragma unroll
            for (int r = 0; r < 4; r++) acc[i][j][r] = 0.f;

    const int lbeg = sp * CH, lend = lbeg + CH;

    float4 pa[2], pb[4];
    #pragma unroll
    for (int it = 0; it < 2; it++) {
        int idx = tid + it * 256;
        int lrow = idx >> 5, mcol4 = (idx & 31) << 2;
        pa[it] = *(const float4*)(Ab + (size_t)(lbeg + lrow) * 1024 + m0 + mcol4);
    }
    #pragma unroll
    for (int it = 0; it < 4; it++) {
        int idx = tid + it * 256;
        int lrow = idx >> 6, dcol4 = (idx & 63) << 2;
        pb[it] = *(const float4*)(Bb + (size_t)(lbeg + lrow) * 1024 + d0 + dcol4);
    }

    for (int l0 = lbeg; l0 < lend; l0 += 16) {
        #pragma unroll
        for (int it = 0; it < 2; it++) {
            int idx = tid + it * 256;
            int lrow = idx >> 5, mcol4 = (idx & 31) << 2;
            *(uint4*)&As[lrow][mcol4] = make_uint4(
                tf32_of(pa[it].x), tf32_of(pa[it].y),
                tf32_of(pa[it].z), tf32_of(pa[it].w));
        }
        #pragma unroll
        for (int it = 0; it < 4; it++) {
            int idx = tid + it * 256;
            int lrow = idx >> 6, dcol4 = (idx & 63) << 2;
            *(uint4*)&Bs[lrow][dcol4] = make_uint4(
                tf32_of(pb[it].x), tf32_of(pb[it].y),
                tf32_of(pb[it].z), tf32_of(pb[it].w));
        }
        __syncthreads();

        if (l0 + 16 < lend) {
            #pragma unroll
            for (int it = 0; it < 2; it++) {
                int idx = tid + it * 256;
                int lrow = idx >> 5, mcol4 = (idx & 31) << 2;
                pa[it] = *(const float4*)(Ab + (size_t)(l0 + 16 + lrow) * 1024 + m0 + mcol4);
            }
            #pragma unroll
            for (int it = 0; it < 4; it++) {
                int idx = tid + it * 256;
                int lrow = idx >> 6, dcol4 = (idx & 63) << 2;
                pb[it] = *(const float4*)(Bb + (size_t)(l0 + 16 + lrow) * 1024 + d0 + dcol4);
            }
        }

        #pragma unroll
        for (int kk = 0; kk < 16; kk += 8) {
            unsigned afr[4][4], bfr[8][2];
            #pragma unroll
            for (int i = 0; i < 4; i++) {
                int mm = warp_m + i * 16 + gid;
                afr[i][0] = As[kk + tig][mm];
                afr[i][1] = As[kk + tig][mm + 8];
                afr[i][2] = As[kk + tig + 4][mm];
                afr[i][3] = As[kk + tig + 4][mm + 8];
            }
            #pragma unroll
            for (int j = 0; j < 8; j++) {
                int nn = warp_n + j * 8 + gid;
                bfr[j][0] = Bs[kk + tig][nn];
                bfr[j][1] = Bs[kk + tig + 4][nn];
            }
            #pragma unroll
            for (int i = 0; i < 4; i++)
                #pragma unroll
                for (int j = 0; j < 8; j++) mma_tf32(acc[i][j], afr[i], bfr[j]);
        }
        __syncthreads();
    }

    float* P = part + (size_t)blockIdx.z * 262144u;
    #pragma unroll
    for (int j = 0; j < 8; j++) {
        int c = d0 + warp_n + j * 8 + tig * 2;
        #pragma unroll
        for (int i = 0; i < 4; i++) {
            int r = m0 + warp_m + i * 16 + gid;
            *(float2*)(P + (size_t)r * 512 + c)       = make_float2(acc[i][j][0], acc[i][j][1]);
            *(float2*)(P + (size_t)(r + 8) * 512 + c) = make_float2(acc[i][j][2], acc[i][j][3]);
        }
    }
}

__global__ void kv_reduce(const float* __restrict__ part, float* __restrict__ kvs) {
    int idx = blockIdx.x * 256 + threadIdx.x;
    int h = idx >> 18;
    int i = idx & 262143;
    const float* p = part + (size_t)(h * KVSPL) * 262144u + i;
    float s = 0.f;
    #pragma unroll
    for (int sp = 0; sp < KVSPL; sp++) s += p[(size_t)sp * 262144u];
    kvs[idx] = s;
}

// ---------------------------------------------------------------------------
// Small reductions / elementwise
// ---------------------------------------------------------------------------
__global__ __launch_bounds__(256) void reduce_to_scalar(
    const float* __restrict__ part, int n, float* __restrict__ out)
{
    __shared__ float sm[8];
    float s = 0.f;
    for (int i = threadIdx.x; i < n; i += 256) s += part[i];
    s = block_reduce_sum(s, sm);
    if (threadIdx.x == 0) *out = s;
}

__global__ __launch_bounds__(256) void ks_reduce512(
    const float* __restrict__ ksp, float* __restrict__ out)
{
    int col = blockIdx.x * 256 + threadIdx.x;
    float s = 0.f;
    for (int by = 0; by < 512; by++) s += ksp[(size_t)by * 1024 + col];
    out[col] = s;
}

__global__ __launch_bounds__(256) void inv_from_qdp(
    const float* __restrict__ qdp, const float* __restrict__ scal,
    float* __restrict__ inv)
{
    int n = blockIdx.x * 256 + threadIdx.x;
    float s = rsqrtf(scal[0] * scal[1]);
    float qd0 = qdp[n] + qdp[65536u + n];
    float qd1 = qdp[2u * 65536u + n] + qdp[3u * 65536u + n];
    inv[2 * n]     = 1.0f / (qd0 * s + 65536.0f);
    inv[2 * n + 1] = 1.0f / (qd1 * s + 65536.0f);
}

__global__ __launch_bounds__(256) void ln_relu(
    const float* __restrict__ x, const float* __restrict__ g,
    const float* __restrict__ b, float* __restrict__ out)
{
    __shared__ float sm[8];
    int n = blockIdx.x, t = threadIdx.x;
    size_t r = (size_t)n * 512;
    float v0 = x[r + t], v1 = x[r + 256 + t];
    float mu = block_reduce_sum(v0 + v1, sm) * (1.f / 512.f);
    float d0 = v0 - mu, d1 = v1 - mu;
    float var = block_reduce_sum(d0 * d0 + d1 * d1, sm) * (1.f / 512.f);
    float rs = rsqrtf(var + 1e-5f);
    float o0 = d0 * rs * g[t] + b[t];
    float o1 = d1 * rs * g[t + 256] + b[t + 256];
    out[r + t]       = fmaxf(o0, 0.f);
    out[r + 256 + t] = fmaxf(o1, 0.f);
}

__global__ __launch_bounds__(256) void combine_res_ln(
    const float* __restrict__ attn, const float* __restrict__ prev,
    const float* __restrict__ g, const float* __restrict__ b,
    float* __restrict__ out)
{
    __shared__ float sm[8];
    int n = blockIdx.x, t = threadIdx.x;
    size_t r1 = (size_t)n * 1024;
    size_t r5 = (size_t)n * 512;
    float val0 = 0.5f * attn[r1 + t]       + 0.5f * prev[r5 + t];
    float val1 = 0.5f * attn[r1 + 256 + t] + 0.5f * prev[r5 + 256 + t];
    float mu = block_reduce_sum(val0 + val1, sm) * (1.f / 512.f);
    float d0 = val0 - mu, d1 = val1 - mu;
    float var = block_reduce_sum(d0 * d0 + d1 * d1, sm) * (1.f / 512.f);
    float rs = rsqrtf(var + 1e-5f);
    out[r5 + t]       = d0 * rs * g[t] + b[t];
    out[r5 + 256 + t] = d1 * rs * g[t + 256] + b[t + 256];
}

// ---------------------------------------------------------------------------
// Launch
// ---------------------------------------------------------------------------
extern "C" void kernel_launch(void* const* d_in, const int* in_sizes, int n_in,
                              void* d_out, int out_size)
{
    (void)in_sizes; (void)n_in; (void)out_size;
    const float* x     = (const float*)d_in[0];
    const float* fc0_w = (const float*)d_in[1];
    const float* fc0_b = (const float*)d_in[2];
    const float* ln0_g = (const float*)d_in[3];
    const float* ln0_b = (const float*)d_in[4];
    const float* wq    = (const float*)d_in[5];
    const float* bq    = (const float*)d_in[6];
    const float* wk    = (const float*)d_in[7];
    const float* bk    = (const float*)d_in[8];
    const float* wv    = (const float*)d_in[9];
    const float* bv    = (const float*)d_in[10];
    const float* lng   = (const float*)d_in[11];
    const float* lnb   = (const float*)d_in[12];
    float* out = (float*)d_out;

    float *qk, *v, *hbuf, *kvp, *kvs, *kvsT, *wt, *ksp, *ks, *red, *scal, *qdp, *inv;
    cudaGetSymbolAddress((void**)&qk,   g_qk);
    cudaGetSymbolAddress((void**)&v,    g_v);
    cudaGetSymbolAddress((void**)&hbuf, g_h);
    cudaGetSymbolAddress((void**)&kvp,  g_kvp);
    cudaGetSymbolAddress((void**)&kvs,  g_kvs);
    cudaGetSymbolAddress((void**)&kvsT, g_kvsT);
    cudaGetSymbolAddress((void**)&wt,   g_wt);
    cudaGetSymbolAddress((void**)&ksp,  g_ksp);
    cudaGetSymbolAddress((void**)&ks,   g_ks);
    cudaGetSymbolAddress((void**)&red,  g_red);
    cudaGetSymbolAddress((void**)&scal, g_scal);
    cudaGetSymbolAddress((void**)&qdp,  g_qdp);
    cudaGetSymbolAddress((void**)&inv,  g_inv);

    dim3 thr(256);
    dim3 tb(32, 8);

    // --- transpose weights into K-major [N][512] layout ---
    transpose_k<<<dim3(16, 16), tb>>>(fc0_w, 512, 512, wt, 1.0f);
    for (int L = 0; L < 2; L++) {
        transpose_k<<<dim3(32, 16), tb>>>(wq + (size_t)L * 524288u, 512, 1024,
                                          wt + (size_t)(1 + 3 * L) * 524288u, 1.0f);
        transpose_k<<<dim3(32, 16), tb>>>(wk + (size_t)L * 524288u, 512, 1024,
                                          wt + (size_t)(2 + 3 * L) * 524288u, 1.0f);
        transpose_k<<<dim3(32, 16), tb>>>(wv + (size_t)L * 524288u, 512, 1024,
                                          wt + (size_t)(3 + 3 * L) * 524288u, 1.0f);
    }

    // --- input projection: h = relu(LN(x @ fc0_w + fc0_b)) ---
    gemm_h_nn<<<dim3(2, 512), thr>>>(x, wt, fc0_b, v, 512, 512, 512,
                                     nullptr, nullptr, nullptr, nullptr);
    ln_relu<<<NPTS, thr>>>(v, ln0_g, ln0_b, hbuf);

    for (int L = 0; L < 2; L++) {
        const float* prev = L ? out : hbuf;
        float* lout = out;
        const float* WQT = wt + (size_t)(1 + 3 * L) * 524288u;
        const float* WKT = wt + (size_t)(2 + 3 * L) * 524288u;
        const float* WVT = wt + (size_t)(3 + 3 * L) * 524288u;
        const float* BQ  = bq + (size_t)L * 1024;
        const float* BKb = bk + (size_t)L * 1024;
        const float* BV  = bv + (size_t)L * 1024;

        // V projection
        gemm_h_nn<<<dim3(4, 512), thr>>>(prev, WVT, BV, v, 512, 512, 1024,
                                         nullptr, nullptr, nullptr, nullptr);
        // K projection (+ ss, + colsum)
        gemm_h_nn<<<dim3(4, 512), thr>>>(prev, WKT, BKb, qk, 512, 512, 1024,
                                         red + 4096, ksp, nullptr, nullptr);
        reduce_to_scalar<<<1, thr>>>(red + 4096, 2048, scal + 1);
        ks_reduce512<<<4, thr>>>(ksp, ks);

        // kvs = K^T V per head (split-K, tf32), then transpose+scale per head
        gemm_tn_kv_v2<<<dim3(2, 4, 32), thr>>>(qk, v, kvp);
        kv_reduce<<<2048, thr>>>(kvp, kvs);
        transpose_k<<<dim3(16, 16), tb>>>(kvs, 512, 512, kvsT, 0.00390625f);
        transpose_k<<<dim3(16, 16), tb>>>(kvs + 262144u, 512, 512,
                                          kvsT + 262144u, 0.00390625f);

        // Q projection (overwrites K) (+ ss, + q.ks partials)
        gemm_h_nn<<<dim3(4, 512), thr>>>(prev, WQT, BQ, qk, 512, 512, 1024,
                                         red, nullptr, ks, qdp);
        reduce_to_scalar<<<1, thr>>>(red, 2048, scal + 0);
        inv_from_qdp<<<256, thr>>>(qdp, scal, inv);

        // fused Q@kvs + attention combine; attn aliases V's head-0 half
        gemm_h_attn<<<dim3(2, 512), thr>>>(qk, kvsT, v, inv, scal, v, 0);
        gemm_h_attn<<<dim3(2, 512), thr>>>(qk + 512, kvsT + 262144u,
                                           v + 512, inv + 1, scal, v, 1);

        // residual + LN
        combine_res_ln<<<NPTS, thr>>>(v, prev,
                                      lng + (size_t)L * 512, lnb + (size_t)L * 512,
                                      lout);
    }
}

// round 14
// speedup vs baseline: 1.3960x; 1.3960x over previous
#include <cuda_runtime.h>
#include <cuda_bf16.h>
#include <cuda_fp16.h>
#include <cstdint>
#include <cstddef>

// ---------------------------------------------------------------------------
// Problem constants
// ---------------------------------------------------------------------------
static const int NPTS  = 65536;
static const int HID   = 512;
static const int HH    = 1024;
static const int KVSPL = 16;

// ---------------------------------------------------------------------------
// Scratch (device globals; no allocation allowed)
// ---------------------------------------------------------------------------
__device__ float g_qk  [65536u * 1024u];      // K, later Q
__device__ float g_v   [65536u * 1024u];      // V; head-0 half later holds attn
__device__ float g_h   [65536u * 512u];       // fc0 output
__device__ float g_kvp [32u * 512u * 512u];   // split-K partials
__device__ float g_kvs [2u * 512u * 512u];    // K^T V per head [m][d]
__device__ float g_kvsT[2u * 512u * 512u];    // transposed [d][m], scaled 2^-8
__device__ float g_wt  [8u * 524288u];        // transposed weights (slots)
__device__ float g_ksp [512u * 1024u];
__device__ float g_ks  [1024u];
__device__ float g_red [8192u];
__device__ float g_scal[2u];
__device__ float g_qdp [4u * 65536u];
__device__ float g_inv [2u * 65536u];

// ---------------------------------------------------------------------------
// Helpers
// ---------------------------------------------------------------------------
__device__ __forceinline__ unsigned tf32_of(float f) {
    unsigned u;
    asm("cvt.rna.tf32.f32 %0, %1;" : "=r"(u) : "f"(f));
    return u;
}

// pack two floats into f16x2 (lo = first arg)
__device__ __forceinline__ unsigned h2pack(float lo, float hi) {
    unsigned u;
    asm("{ .reg .f16 l, h; cvt.rn.f16.f32 l, %1; cvt.rn.f16.f32 h, %2; "
        "mov.b32 %0, {l, h}; }" : "=r"(u) : "f"(lo), "f"(hi));
    return u;
}

__device__ __forceinline__ void mma_tf32(float c[4], const unsigned a[4],
                                         const unsigned b[2]) {
    asm volatile(
        "mma.sync.aligned.m16n8k8.row.col.f32.tf32.tf32.f32 "
        "{%0,%1,%2,%3},{%4,%5,%6,%7},{%8,%9},{%0,%1,%2,%3};\n"
        : "+f"(c[0]), "+f"(c[1]), "+f"(c[2]), "+f"(c[3])
        : "r"(a[0]), "r"(a[1]), "r"(a[2]), "r"(a[3]), "r"(b[0]), "r"(b[1]));
}

__device__ __forceinline__ void mma_f16(float c[4], const unsigned a[4],
                                        const unsigned b[2]) {
    asm volatile(
        "mma.sync.aligned.m16n8k16.row.col.f32.f16.f16.f32 "
        "{%0,%1,%2,%3},{%4,%5,%6,%7},{%8,%9},{%0,%1,%2,%3};\n"
        : "+f"(c[0]), "+f"(c[1]), "+f"(c[2]), "+f"(c[3])
        : "r"(a[0]), "r"(a[1]), "r"(a[2]), "r"(a[3]), "r"(b[0]), "r"(b[1]));
}

__device__ __forceinline__ float block_reduce_sum(float v, float* sm) {
    int tid = threadIdx.x;
    int lane = tid & 31, wid = tid >> 5;
    #pragma unroll
    for (int o = 16; o > 0; o >>= 1) v += __shfl_down_sync(0xffffffffu, v, o);
    __syncthreads();
    if (lane == 0) sm[wid] = v;
    __syncthreads();
    if (tid == 0) {
        float s = 0.f;
        #pragma unroll
        for (int i = 0; i < 8; i++) s += sm[i];
        sm[0] = s;
    }
    __syncthreads();
    return sm[0];
}

// ---------------------------------------------------------------------------
// Tiled transpose with scale: out[C][R] = scale * in[R][C]^T
// block (32,8), grid (C/32, R/32)
// ---------------------------------------------------------------------------
__global__ void transpose_k(const float* __restrict__ in, int R, int C,
                            float* __restrict__ out, float scale)
{
    __shared__ float t[32][33];
    int c0 = blockIdx.x * 32, r0 = blockIdx.y * 32;
    int x = threadIdx.x, y = threadIdx.y;
    #pragma unroll
    for (int i = 0; i < 32; i += 8)
        t[y + i][x] = in[(size_t)(r0 + y + i) * C + c0 + x];
    __syncthreads();
    #pragma unroll
    for (int i = 0; i < 32; i += 8)
        out[(size_t)(c0 + y + i) * R + r0 + x] = t[x][y + i] * scale;
}

// ===========================================================================
// FP16 GEMM core with register-prefetch pipeline (round-9 structure):
// per tile: STS(t) -> sync -> LDG(t+1) -> MMA(t) -> sync.
// Block tile 128(M) x 256(N), BK=32, 256 threads.
// 8 warps 2(M) x 4(N); warp tile 64x64 -> 4x8 m16n8k16 frags (fp32 accum).
// A [M,*] row-major fp32 (lda); BT [Ntot][512] row-major fp32 (K-major).
// Fused epilogue options: ss / colsum / q.ks row-dot.
// ===========================================================================
__global__ __launch_bounds__(256) void gemm_h_nn(
    const float* __restrict__ A, const float* __restrict__ BT,
    const float* __restrict__ bias, float* __restrict__ C,
    int K, int lda, int ldc,
    float* __restrict__ ss_out,
    float* __restrict__ colsum_out,
    const float* __restrict__ ksvec,
    float* __restrict__ qdp_out)
{
    __shared__ unsigned As[128 * 20];   // [m][k2] half2, stride 20 (16 used)
    __shared__ unsigned Bs[256 * 20];   // [n][k2] half2
    __shared__ float epism[4096];
    __shared__ float rsm[8];

    const int tid = threadIdx.x;
    const int lane = tid & 31;
    const int wid = tid >> 5;
    const int gid = lane >> 2, tig = lane & 3;
    const int warp_m = (wid & 1) * 64;
    const int warp_n = (wid >> 1) * 64;
    const int m0 = blockIdx.y * 128;
    const int n0 = blockIdx.x * 256;
    const int T = K >> 5;

    // fill addressing: 8 threads per 32-float row
    const int fr = tid >> 3;         // row  (+ it*32 for A, + it*32 for B)
    const int fc = (tid & 7) * 4;    // col

    float acc[4][8][4];
    #pragma unroll
    for (int i = 0; i < 4; i++)
        #pragma unroll
        for (int j = 0; j < 8; j++)
            #pragma unroll
            for (int r = 0; r < 4; r++) acc[i][j][r] = 0.f;

    float4 pa[4], pb[8];
    // prologue: load tile 0 into registers
    #pragma unroll
    for (int it = 0; it < 4; it++)
        pa[it] = *(const float4*)(A + (size_t)(m0 + fr + it * 32) * lda + fc);
    #pragma unroll
    for (int it = 0; it < 8; it++)
        pb[it] = *(const float4*)(BT + (size_t)(n0 + fr + it * 32) * 512 + fc);

    for (int t = 0; t < T; t++) {
        // store current regs (cvt to half2) into smem
        #pragma unroll
        for (int it = 0; it < 4; it++) {
            uint2 u;
            u.x = h2pack(pa[it].x, pa[it].y);
            u.y = h2pack(pa[it].z, pa[it].w);
            *(uint2*)&As[(fr + it * 32) * 20 + (fc >> 1)] = u;
        }
        #pragma unroll
        for (int it = 0; it < 8; it++) {
            uint2 u;
            u.x = h2pack(pb[it].x, pb[it].y);
            u.y = h2pack(pb[it].z, pb[it].w);
            *(uint2*)&Bs[(fr + it * 32) * 20 + (fc >> 1)] = u;
        }
        __syncthreads();

        // prefetch next tile while computing this one
        if (t + 1 < T) {
            const int k0 = (t + 1) * 32;
            #pragma unroll
            for (int it = 0; it < 4; it++)
                pa[it] = *(const float4*)(A + (size_t)(m0 + fr + it * 32) * lda + k0 + fc);
            #pragma unroll
            for (int it = 0; it < 8; it++)
                pb[it] = *(const float4*)(BT + (size_t)(n0 + fr + it * 32) * 512 + k0 + fc);
        }

        #pragma unroll
        for (int kk2 = 0; kk2 < 16; kk2 += 8) {
            unsigned afr[4][4], bfr[8][2];
            #pragma unroll
            for (int i = 0; i < 4; i++) {
                int mm = warp_m + i * 16 + gid;
                afr[i][0] = As[mm * 20 + kk2 + tig];
                afr[i][1] = As[(mm + 8) * 20 + kk2 + tig];
                afr[i][2] = As[mm * 20 + kk2 + tig + 4];
                afr[i][3] = As[(mm + 8) * 20 + kk2 + tig + 4];
            }
            #pragma unroll
            for (int j = 0; j < 8; j++) {
                int nn = warp_n + j * 8 + gid;
                bfr[j][0] = Bs[nn * 20 + kk2 + tig];
                bfr[j][1] = Bs[nn * 20 + kk2 + tig + 4];
            }
            #pragma unroll
            for (int i = 0; i < 4; i++)
                #pragma unroll
                for (int j = 0; j < 8; j++) mma_f16(acc[i][j], afr[i], bfr[j]);
        }
        __syncthreads();
    }

    // ---- epilogue: bias add, store, fused reductions ----
    const bool do_cs = (colsum_out != nullptr);
    const bool do_qd = (qdp_out != nullptr);
    float ss = 0.f;
    float qd[4][2];
    #pragma unroll
    for (int i = 0; i < 4; i++) { qd[i][0] = 0.f; qd[i][1] = 0.f; }

    #pragma unroll
    for (int j = 0; j < 8; j++) {
        int c = n0 + warp_n + j * 8 + tig * 2;
        float bx = bias ? bias[c] : 0.f;
        float by = bias ? bias[c + 1] : 0.f;
        float ks0 = 0.f, ks1 = 0.f;
        if (do_qd) { ks0 = ksvec[c]; ks1 = ksvec[c + 1]; }
        float cs0 = 0.f, cs1 = 0.f;
        #pragma unroll
        for (int i = 0; i < 4; i++) {
            int r = m0 + warp_m + i * 16 + gid;
            float x0 = acc[i][j][0] + bx, x1 = acc[i][j][1] + by;
            float x2 = acc[i][j][2] + bx, x3 = acc[i][j][3] + by;
            *(float2*)(C + (size_t)r * ldc + c)       = make_float2(x0, x1);
            *(float2*)(C + (size_t)(r + 8) * ldc + c) = make_float2(x2, x3);
            ss += x0 * x0 + x1 * x1 + x2 * x2 + x3 * x3;
            cs0 += x0 + x2; cs1 += x1 + x3;
            qd[i][0] += x0 * ks0 + x1 * ks1;
            qd[i][1] += x2 * ks0 + x3 * ks1;
        }
        if (do_cs) {
            epism[(tid * 8 + j) * 2 + 0] = cs0;
            epism[(tid * 8 + j) * 2 + 1] = cs1;
        }
    }

    if (do_cs) {
        __syncthreads();
        int c = tid;
        int wn = c >> 6, j = (c >> 3) & 7, tg = (c & 7) >> 1, e = c & 1;
        float s = 0.f;
        #pragma unroll
        for (int wm = 0; wm < 2; wm++)
            #pragma unroll
            for (int g = 0; g < 8; g++) {
                int t2 = (2 * wn + wm) * 32 + g * 4 + tg;
                s += epism[(t2 * 8 + j) * 2 + e];
            }
        colsum_out[(size_t)blockIdx.y * 1024 + n0 + c] = s;
    }

    if (do_qd) {
        __syncthreads();
        #pragma unroll
        for (int i = 0; i < 4; i++) {
            epism[(tid * 4 + i) * 2 + 0] = qd[i][0];
            epism[(tid * 4 + i) * 2 + 1] = qd[i][1];
        }
        __syncthreads();
        if (tid < 128) {
            int rl = tid;
            int wm = rl >> 6, rem = rl & 63;
            int i = rem >> 4, hf = (rem >> 3) & 1, g = rem & 7;
            float s = 0.f;
            #pragma unroll
            for (int wn = 0; wn < 4; wn++)
                #pragma unroll
                for (int tg = 0; tg < 4; tg++) {
                    int t2 = (2 * wn + wm) * 32 + g * 4 + tg;
                    s += epism[(t2 * 4 + i) * 2 + hf];
                }
            qdp_out[(size_t)blockIdx.x * 65536u + m0 + rl] = s;
        }
    }

    if (ss_out) {
        float s = block_reduce_sum(ss, rsm);
        if (tid == 0) ss_out[blockIdx.y * gridDim.x + blockIdx.x] = s;
    }
}

// ---------------------------------------------------------------------------
// FP16 fused attention GEMM (same prefetch pipeline):
//   C[r,c] (+)= 0.5 * inv[r] * ( (A@B)[r,c] * (s*256)  +  65536 * V[r,c] )
// BT = kvsT pre-scaled by 2^-8; 2^8 folded into s here.
// A = q head slice (lda 1024); grid (2, 512), N=512, K=512.
// ---------------------------------------------------------------------------
__global__ __launch_bounds__(256) void gemm_h_attn(
    const float* __restrict__ A, const float* __restrict__ BT,
    const float* __restrict__ Vb, const float* __restrict__ invp,
    const float* __restrict__ scal, float* __restrict__ C, int beta)
{
    __shared__ unsigned As[128 * 20];
    __shared__ unsigned Bs[256 * 20];

    const int tid = threadIdx.x;
    const int lane = tid & 31;
    const int wid = tid >> 5;
    const int gid = lane >> 2, tig = lane & 3;
    const int warp_m = (wid & 1) * 64;
    const int warp_n = (wid >> 1) * 64;
    const int m0 = blockIdx.y * 128;
    const int n0 = blockIdx.x * 256;

    const int fr = tid >> 3;
    const int fc = (tid & 7) * 4;

    float acc[4][8][4];
    #pragma unroll
    for (int i = 0; i < 4; i++)
        #pragma unroll
        for (int j = 0; j < 8; j++)
            #pragma unroll
            for (int r = 0; r < 4; r++) acc[i][j][r] = 0.f;

    float4 pa[4], pb[8];
    #pragma unroll
    for (int it = 0; it < 4; it++)
        pa[it] = *(const float4*)(A + (size_t)(m0 + fr + it * 32) * 1024 + fc);
    #pragma unroll
    for (int it = 0; it < 8; it++)
        pb[it] = *(const float4*)(BT + (size_t)(n0 + fr + it * 32) * 512 + fc);

    for (int t = 0; t < 16; t++) {
        #pragma unroll
        for (int it = 0; it < 4; it++) {
            uint2 u;
            u.x = h2pack(pa[it].x, pa[it].y);
            u.y = h2pack(pa[it].z, pa[it].w);
            *(uint2*)&As[(fr + it * 32) * 20 + (fc >> 1)] = u;
        }
        #pragma unroll
        for (int it = 0; it < 8; it++) {
            uint2 u;
            u.x = h2pack(pb[it].x, pb[it].y);
            u.y = h2pack(pb[it].z, pb[it].w);
            *(uint2*)&Bs[(fr + it * 32) * 20 + (fc >> 1)] = u;
        }
        __syncthreads();

        if (t + 1 < 16) {
            const int k0 = (t + 1) * 32;
            #pragma unroll
            for (int it = 0; it < 4; it++)
                pa[it] = *(const float4*)(A + (size_t)(m0 + fr + it * 32) * 1024 + k0 + fc);
            #pragma unroll
            for (int it = 0; it < 8; it++)
                pb[it] = *(const float4*)(BT + (size_t)(n0 + fr + it * 32) * 512 + k0 + fc);
        }

        #pragma unroll
        for (int kk2 = 0; kk2 < 16; kk2 += 8) {
            unsigned afr[4][4], bfr[8][2];
            #pragma unroll
            for (int i = 0; i < 4; i++) {
                int mm = warp_m + i * 16 + gid;
                afr[i][0] = As[mm * 20 + kk2 + tig];
                afr[i][1] = As[(mm + 8) * 20 + kk2 + tig];
                afr[i][2] = As[mm * 20 + kk2 + tig + 4];
                afr[i][3] = As[(mm + 8) * 20 + kk2 + tig + 4];
            }
            #pragma unroll
            for (int j = 0; j < 8; j++) {
                int nn = warp_n + j * 8 + gid;
                bfr[j][0] = Bs[nn * 20 + kk2 + tig];
                bfr[j][1] = Bs[nn * 20 + kk2 + tig + 4];
            }
            #pragma unroll
            for (int i = 0; i < 4; i++)
                #pragma unroll
                for (int j = 0; j < 8; j++) mma_f16(acc[i][j], afr[i], bfr[j]);
        }
        __syncthreads();
    }

    // 2^8 compensates the 2^-8 pre-scale on kvsT (exact power-of-two)
    const float s = rsqrtf(scal[0] * scal[1]) * 256.0f;
    #pragma unroll
    for (int j = 0; j < 8; j++) {
        int c = n0 + warp_n + j * 8 + tig * 2;
        #pragma unroll
        for (int i = 0; i < 4; i++) {
            int r = m0 + warp_m + i * 16 + gid;
            float iv0 = invp[2 * (size_t)r];
            float iv1 = invp[2 * (size_t)(r + 8)];
            float2 va  = *(const float2*)(Vb + (size_t)r * 1024 + c);
            float2 vbv = *(const float2*)(Vb + (size_t)(r + 8) * 1024 + c);
            float x0 = (acc[i][j][0] * s + 65536.f * va.x)  * iv0 * 0.5f;
            float x1 = (acc[i][j][1] * s + 65536.f * va.y)  * iv0 * 0.5f;
            float x2 = (acc[i][j][2] * s + 65536.f * vbv.x) * iv1 * 0.5f;
            float x3 = (acc[i][j][3] * s + 65536.f * vbv.y) * iv1 * 0.5f;
            float* c0 = C + (size_t)r * 1024 + c;
            float* c1 = C + (size_t)(r + 8) * 1024 + c;
            if (beta) {
                float2 o0 = *(float2*)c0, o1 = *(float2*)c1;
                x0 += o0.x; x1 += o0.y; x2 += o1.x; x3 += o1.y;
            }
            *(float2*)c0 = make_float2(x0, x1);
            *(float2*)c1 = make_float2(x2, x3);
        }
    }
}

// ---------------------------------------------------------------------------
// TN GEMM for kvs (tf32 v2, known-good): C[m,d] = sum_l K[l,m]*V[l,d], split-K
// ---------------------------------------------------------------------------
__global__ __launch_bounds__(256) void gemm_tn_kv_v2(
    const float* __restrict__ Kp, const float* __restrict__ Vp,
    float* __restrict__ part)
{
    __shared__ unsigned As[16][264];
    __shared__ unsigned Bs[16][264];

    const int tid = threadIdx.x;
    const int lane = tid & 31;
    const int wid = tid >> 5;
    const int gid = lane >> 2, tig = lane & 3;
    const int warp_m = (wid & 1) * 64;
    const int warp_n = (wid >> 1) * 64;
    const int d0 = blockIdx.x * 256;
    const int m0 = blockIdx.y * 128;
    const int h  = blockIdx.z >> 4;
    const int sp = blockIdx.z & 15;
    const int CH = NPTS / KVSPL;

    const float* Ab = Kp + (size_t)h * 512;
    const float* Bb = Vp + (size_t)h * 512;

    float acc[4][8][4];
    #pragma unroll
    for (int i = 0; i < 4; i++)
        #pragma unroll
        for (int j = 0; j < 8; j++)
            #pragma unroll
            for (int r = 0; r < 4; r++) acc[i][j][r] = 0.f;

    const int lbeg = sp * CH, lend = lbeg + CH;

    float4 pa[2], pb[4];
    #pragma unroll
    for (int it = 0; it < 2; it++) {
        int idx = tid + it * 256;
        int lrow = idx >> 5, mcol4 = (idx & 31) << 2;
        pa[it] = *(const float4*)(Ab + (size_t)(lbeg + lrow) * 1024 + m0 + mcol4);
    }
    #pragma unroll
    for (int it = 0; it < 4; it++) {
        int idx = tid + it * 256;
        int lrow = idx >> 6, dcol4 = (idx & 63) << 2;
        pb[it] = *(const float4*)(Bb + (size_t)(lbeg + lrow) * 1024 + d0 + dcol4);
    }

    for (int l0 = lbeg; l0 < lend; l0 += 16) {
        #pragma unroll
        for (int it = 0; it < 2; it++) {
            int idx = tid + it * 256;
            int lrow = idx >> 5, mcol4 = (idx & 31) << 2;
            *(uint4*)&As[lrow][mcol4] = make_uint4(
                tf32_of(pa[it].x), tf32_of(pa[it].y),
                tf32_of(pa[it].z), tf32_of(pa[it].w));
        }
        #pragma unroll
        for (int it = 0; it < 4; it++) {
            int idx = tid + it * 256;
            int lrow = idx >> 6, dcol4 = (idx & 63) << 2;
            *(uint4*)&Bs[lrow][dcol4] = make_uint4(
                tf32_of(pb[it].x), tf32_of(pb[it].y),
                tf32_of(pb[it].z), tf32_of(pb[it].w));
        }
        __syncthreads();

        if (l0 + 16 < lend) {
            #pragma unroll
            for (int it = 0; it < 2; it++) {
                int idx = tid + it * 256;
                int lrow = idx >> 5, mcol4 = (idx & 31) << 2;
                pa[it] = *(const float4*)(Ab + (size_t)(l0 + 16 + lrow) * 1024 + m0 + mcol4);
            }
            #pragma unroll
            for (int it = 0; it < 4; it++) {
                int idx = tid + it * 256;
                int lrow = idx >> 6, dcol4 = (idx & 63) << 2;
                pb[it] = *(const float4*)(Bb + (size_t)(l0 + 16 + lrow) * 1024 + d0 + dcol4);
            }
        }

        #pragma unroll
        for (int kk = 0; kk < 16; kk += 8) {
            unsigned afr[4][4], bfr[8][2];
            #pragma unroll
            for (int i = 0; i < 4; i++) {
                int mm = warp_m + i * 16 + gid;
                afr[i][0] = As[kk + tig][mm];
                afr[i][1] = As[kk + tig][mm + 8];
                afr[i][2] = As[kk + tig + 4][mm];
                afr[i][3] = As[kk + tig + 4][mm + 8];
            }
            #pragma unroll
            for (int j = 0; j < 8; j++) {
                int nn = warp_n + j * 8 + gid;
                bfr[j][0] = Bs[kk + tig][nn];
                bfr[j][1] = Bs[kk + tig + 4][nn];
            }
            #pragma unroll
            for (int i = 0; i < 4; i++)
                #pragma unroll
                for (int j = 0; j < 8; j++) mma_tf32(acc[i][j], afr[i], bfr[j]);
        }
        __syncthreads();
    }

    float* P = part + (size_t)blockIdx.z * 262144u;
    #pragma unroll
    for (int j = 0; j < 8; j++) {
        int c = d0 + warp_n + j * 8 + tig * 2;
        #pragma unroll
        for (int i = 0; i < 4; i++) {
            int r = m0 + warp_m + i * 16 + gid;
            *(float2*)(P + (size_t)r * 512 + c)       = make_float2(acc[i][j][0], acc[i][j][1]);
            *(float2*)(P + (size_t)(r + 8) * 512 + c) = make_float2(acc[i][j][2], acc[i][j][3]);
        }
    }
}

__global__ void kv_reduce(const float* __restrict__ part, float* __restrict__ kvs) {
    int idx = blockIdx.x * 256 + threadIdx.x;
    int h = idx >> 18;
    int i = idx & 262143;
    const float* p = part + (size_t)(h * KVSPL) * 262144u + i;
    float s = 0.f;
    #pragma unroll
    for (int sp = 0; sp < KVSPL; sp++) s += p[(size_t)sp * 262144u];
    kvs[idx] = s;
}

// ---------------------------------------------------------------------------
// Small reductions / elementwise
// ---------------------------------------------------------------------------
__global__ __launch_bounds__(256) void reduce_to_scalar(
    const float* __restrict__ part, int n, float* __restrict__ out)
{
    __shared__ float sm[8];
    float s = 0.f;
    for (int i = threadIdx.x; i < n; i += 256) s += part[i];
    s = block_reduce_sum(s, sm);
    if (threadIdx.x == 0) *out = s;
}

__global__ __launch_bounds__(256) void ks_reduce512(
    const float* __restrict__ ksp, float* __restrict__ out)
{
    int col = blockIdx.x * 256 + threadIdx.x;
    float s = 0.f;
    for (int by = 0; by < 512; by++) s += ksp[(size_t)by * 1024 + col];
    out[col] = s;
}

__global__ __launch_bounds__(256) void inv_from_qdp(
    const float* __restrict__ qdp, const float* __restrict__ scal,
    float* __restrict__ inv)
{
    int n = blockIdx.x * 256 + threadIdx.x;
    float s = rsqrtf(scal[0] * scal[1]);
    float qd0 = qdp[n] + qdp[65536u + n];
    float qd1 = qdp[2u * 65536u + n] + qdp[3u * 65536u + n];
    inv[2 * n]     = 1.0f / (qd0 * s + 65536.0f);
    inv[2 * n + 1] = 1.0f / (qd1 * s + 65536.0f);
}

__global__ __launch_bounds__(256) void ln_relu(
    const float* __restrict__ x, const float* __restrict__ g,
    const float* __restrict__ b, float* __restrict__ out)
{
    __shared__ float sm[8];
    int n = blockIdx.x, t = threadIdx.x;
    size_t r = (size_t)n * 512;
    float v0 = x[r + t], v1 = x[r + 256 + t];
    float mu = block_reduce_sum(v0 + v1, sm) * (1.f / 512.f);
    float d0 = v0 - mu, d1 = v1 - mu;
    float var = block_reduce_sum(d0 * d0 + d1 * d1, sm) * (1.f / 512.f);
    float rs = rsqrtf(var + 1e-5f);
    float o0 = d0 * rs * g[t] + b[t];
    float o1 = d1 * rs * g[t + 256] + b[t + 256];
    out[r + t]       = fmaxf(o0, 0.f);
    out[r + 256 + t] = fmaxf(o1, 0.f);
}

__global__ __launch_bounds__(256) void combine_res_ln(
    const float* __restrict__ attn, const float* __restrict__ prev,
    const float* __restrict__ g, const float* __restrict__ b,
    float* __restrict__ out)
{
    __shared__ float sm[8];
    int n = blockIdx.x, t = threadIdx.x;
    size_t r1 = (size_t)n * 1024;
    size_t r5 = (size_t)n * 512;
    float val0 = 0.5f * attn[r1 + t]       + 0.5f * prev[r5 + t];
    float val1 = 0.5f * attn[r1 + 256 + t] + 0.5f * prev[r5 + 256 + t];
    float mu = block_reduce_sum(val0 + val1, sm) * (1.f / 512.f);
    float d0 = val0 - mu, d1 = val1 - mu;
    float var = block_reduce_sum(d0 * d0 + d1 * d1, sm) * (1.f / 512.f);
    float rs = rsqrtf(var + 1e-5f);
    out[r5 + t]       = d0 * rs * g[t] + b[t];
    out[r5 + 256 + t] = d1 * rs * g[t + 256] + b[t + 256];
}

// ---------------------------------------------------------------------------
// Launch
// ---------------------------------------------------------------------------
extern "C" void kernel_launch(void* const* d_in, const int* in_sizes, int n_in,
                              void* d_out, int out_size)
{
    (void)in_sizes; (void)n_in; (void)out_size;
    const float* x     = (const float*)d_in[0];
    const float* fc0_w = (const float*)d_in[1];
    const float* fc0_b = (const float*)d_in[2];
    const float* ln0_g = (const float*)d_in[3];
    const float* ln0_b = (const float*)d_in[4];
    const float* wq    = (const float*)d_in[5];
    const float* bq    = (const float*)d_in[6];
    const float* wk    = (const float*)d_in[7];
    const float* bk    = (const float*)d_in[8];
    const float* wv    = (const float*)d_in[9];
    const float* bv    = (const float*)d_in[10];
    const float* lng   = (const float*)d_in[11];
    const float* lnb   = (const float*)d_in[12];
    float* out = (float*)d_out;

    float *qk, *v, *hbuf, *kvp, *kvs, *kvsT, *wt, *ksp, *ks, *red, *scal, *qdp, *inv;
    cudaGetSymbolAddress((void**)&qk,   g_qk);
    cudaGetSymbolAddress((void**)&v,    g_v);
    cudaGetSymbolAddress((void**)&hbuf, g_h);
    cudaGetSymbolAddress((void**)&kvp,  g_kvp);
    cudaGetSymbolAddress((void**)&kvs,  g_kvs);
    cudaGetSymbolAddress((void**)&kvsT, g_kvsT);
    cudaGetSymbolAddress((void**)&wt,   g_wt);
    cudaGetSymbolAddress((void**)&ksp,  g_ksp);
    cudaGetSymbolAddress((void**)&ks,   g_ks);
    cudaGetSymbolAddress((void**)&red,  g_red);
    cudaGetSymbolAddress((void**)&scal, g_scal);
    cudaGetSymbolAddress((void**)&qdp,  g_qdp);
    cudaGetSymbolAddress((void**)&inv,  g_inv);

    dim3 thr(256);
    dim3 tb(32, 8);

    // --- transpose weights into K-major [N][512] layout ---
    transpose_k<<<dim3(16, 16), tb>>>(fc0_w, 512, 512, wt, 1.0f);
    for (int L = 0; L < 2; L++) {
        transpose_k<<<dim3(32, 16), tb>>>(wq + (size_t)L * 524288u, 512, 1024,
                                          wt + (size_t)(1 + 3 * L) * 524288u, 1.0f);
        transpose_k<<<dim3(32, 16), tb>>>(wk + (size_t)L * 524288u, 512, 1024,
                                          wt + (size_t)(2 + 3 * L) * 524288u, 1.0f);
        transpose_k<<<dim3(32, 16), tb>>>(wv + (size_t)L * 524288u, 512, 1024,
                                          wt + (size_t)(3 + 3 * L) * 524288u, 1.0f);
    }

    // --- input projection: h = relu(LN(x @ fc0_w + fc0_b)) ---
    gemm_h_nn<<<dim3(2, 512), thr>>>(x, wt, fc0_b, v, 512, 512, 512,
                                     nullptr, nullptr, nullptr, nullptr);
    ln_relu<<<NPTS, thr>>>(v, ln0_g, ln0_b, hbuf);

    for (int L = 0; L < 2; L++) {
        const float* prev = L ? out : hbuf;
        float* lout = out;
        const float* WQT = wt + (size_t)(1 + 3 * L) * 524288u;
        const float* WKT = wt + (size_t)(2 + 3 * L) * 524288u;
        const float* WVT = wt + (size_t)(3 + 3 * L) * 524288u;
        const float* BQ  = bq + (size_t)L * 1024;
        const float* BKb = bk + (size_t)L * 1024;
        const float* BV  = bv + (size_t)L * 1024;

        // V projection
        gemm_h_nn<<<dim3(4, 512), thr>>>(prev, WVT, BV, v, 512, 512, 1024,
                                         nullptr, nullptr, nullptr, nullptr);
        // K projection (+ ss, + colsum)
        gemm_h_nn<<<dim3(4, 512), thr>>>(prev, WKT, BKb, qk, 512, 512, 1024,
                                         red + 4096, ksp, nullptr, nullptr);
        reduce_to_scalar<<<1, thr>>>(red + 4096, 2048, scal + 1);
        ks_reduce512<<<4, thr>>>(ksp, ks);

        // kvs = K^T V per head (split-K, tf32), then transpose+scale per head
        gemm_tn_kv_v2<<<dim3(2, 4, 32), thr>>>(qk, v, kvp);
        kv_reduce<<<2048, thr>>>(kvp, kvs);
        transpose_k<<<dim3(16, 16), tb>>>(kvs, 512, 512, kvsT, 0.00390625f);
        transpose_k<<<dim3(16, 16), tb>>>(kvs + 262144u, 512, 512,
                                          kvsT + 262144u, 0.00390625f);

        // Q projection (overwrites K) (+ ss, + q.ks partials)
        gemm_h_nn<<<dim3(4, 512), thr>>>(prev, WQT, BQ, qk, 512, 512, 1024,
                                         red, nullptr, ks, qdp);
        reduce_to_scalar<<<1, thr>>>(red, 2048, scal + 0);
        inv_from_qdp<<<256, thr>>>(qdp, scal, inv);

        // fused Q@kvs + attention combine; attn aliases V's head-0 half
        gemm_h_attn<<<dim3(2, 512), thr>>>(qk, kvsT, v, inv, scal, v, 0);
        gemm_h_attn<<<dim3(2, 512), thr>>>(qk + 512, kvsT + 262144u,
                                           v + 512, inv + 1, scal, v, 1);

        // residual + LN
        combine_res_ln<<<NPTS, thr>>>(v, prev,
                                      lng + (size_t)L * 512, lnb + (size_t)L * 512,
                                      lout);
    }
}

// round 16
// speedup vs baseline: 1.9840x; 1.4212x over previous
#include <cuda_runtime.h>
#include <cuda_bf16.h>
#include <cuda_fp16.h>
#include <cstdint>
#include <cstddef>

// ---------------------------------------------------------------------------
// Problem constants
// ---------------------------------------------------------------------------
static const int NPTS  = 65536;
static const int HID   = 512;
static const int HH    = 1024;
static const int KVSPL = 16;

// ---------------------------------------------------------------------------
// Scratch (device globals; no allocation allowed)
// ---------------------------------------------------------------------------
__device__ float  g_qk  [65536u * 1024u];     // K fp32 (for kv gemm)
__device__ float  g_v   [65536u * 1024u];     // V; head-0 half later holds attn
__device__ float  g_h   [65536u * 512u];      // fc0 output fp32 (residual)
__device__ float  g_kvp [32u * 512u * 512u];  // split-K partials
__device__ float  g_kvs [2u * 512u * 512u];   // K^T V per head [m][d]
__device__ __half g_kvsT16[2u * 262144u];     // [d][m] fp16, scaled 2^-8
__device__ __half g_wt16[7u * 524288u];       // transposed fp16 weights
__device__ __half g_x16 [65536u * 512u];      // x in fp16
__device__ __half g_a16 [65536u * 512u];      // prev activations fp16
__device__ __half g_q16 [65536u * 1024u];     // Q fp16
__device__ float  g_ksp [512u * 1024u];
__device__ float  g_ks  [1024u];
__device__ float  g_red [8192u];
__device__ float  g_scal[2u];
__device__ float  g_qdp [4u * 65536u];
__device__ float  g_inv [2u * 65536u];

// ---------------------------------------------------------------------------
// Helpers
// ---------------------------------------------------------------------------
__device__ __forceinline__ unsigned tf32_of(float f) {
    unsigned u;
    asm("cvt.rna.tf32.f32 %0, %1;" : "=r"(u) : "f"(f));
    return u;
}

__device__ __forceinline__ unsigned h2pack(float lo, float hi) {
    unsigned u;
    asm("{ .reg .f16 l, h; cvt.rn.f16.f32 l, %1; cvt.rn.f16.f32 h, %2; "
        "mov.b32 %0, {l, h}; }" : "=r"(u) : "f"(lo), "f"(hi));
    return u;
}

__device__ __forceinline__ void mma_tf32(float c[4], const unsigned a[4],
                                         const unsigned b[2]) {
    asm volatile(
        "mma.sync.aligned.m16n8k8.row.col.f32.tf32.tf32.f32 "
        "{%0,%1,%2,%3},{%4,%5,%6,%7},{%8,%9},{%0,%1,%2,%3};\n"
        : "+f"(c[0]), "+f"(c[1]), "+f"(c[2]), "+f"(c[3])
        : "r"(a[0]), "r"(a[1]), "r"(a[2]), "r"(a[3]), "r"(b[0]), "r"(b[1]));
}

__device__ __forceinline__ void mma_f16(float c[4], const unsigned a[4],
                                        const unsigned b[2]) {
    asm volatile(
        "mma.sync.aligned.m16n8k16.row.col.f32.f16.f16.f32 "
        "{%0,%1,%2,%3},{%4,%5,%6,%7},{%8,%9},{%0,%1,%2,%3};\n"
        : "+f"(c[0]), "+f"(c[1]), "+f"(c[2]), "+f"(c[3])
        : "r"(a[0]), "r"(a[1]), "r"(a[2]), "r"(a[3]), "r"(b[0]), "r"(b[1]));
}

__device__ __forceinline__ float block_reduce_sum(float v, float* sm) {
    int tid = threadIdx.x;
    int lane = tid & 31, wid = tid >> 5;
    #pragma unroll
    for (int o = 16; o > 0; o >>= 1) v += __shfl_down_sync(0xffffffffu, v, o);
    __syncthreads();
    if (lane == 0) sm[wid] = v;
    __syncthreads();
    if (tid == 0) {
        float s = 0.f;
        #pragma unroll
        for (int i = 0; i < 8; i++) s += sm[i];
        sm[0] = s;
    }
    __syncthreads();
    return sm[0];
}

// ---------------------------------------------------------------------------
// fp32 -> fp16 bulk convert (float4 -> 4 halves per thread)
// ---------------------------------------------------------------------------
__global__ __launch_bounds__(256) void cvt_f2h(
    const float* __restrict__ in, __half* __restrict__ out, int n4)
{
    int i = blockIdx.x * 256 + threadIdx.x;
    if (i < n4) {
        float4 v = ((const float4*)in)[i];
        uint2 u;
        u.x = h2pack(v.x, v.y);
        u.y = h2pack(v.z, v.w);
        ((uint2*)out)[i] = u;
    }
}

// ---------------------------------------------------------------------------
// Tiled transpose fp32 -> fp16 with scale: out[C][R] = (half)(scale * in^T)
// block (32,8), grid (C/32, R/32)
// ---------------------------------------------------------------------------
__global__ void transpose_h(const float* __restrict__ in, int R, int C,
                            __half* __restrict__ out, float scale)
{
    __shared__ float t[32][33];
    int c0 = blockIdx.x * 32, r0 = blockIdx.y * 32;
    int x = threadIdx.x, y = threadIdx.y;
    #pragma unroll
    for (int i = 0; i < 32; i += 8)
        t[y + i][x] = in[(size_t)(r0 + y + i) * C + c0 + x];
    __syncthreads();
    #pragma unroll
    for (int i = 0; i < 32; i += 8)
        out[(size_t)(c0 + y + i) * R + r0 + x] = __float2half(t[x][y + i] * scale);
}

// ===========================================================================
// FP16-operand GEMM core (register-prefetch pipeline, no cvt in fill):
// per tile: STS(t) -> sync -> LDG(t+1) -> MMA(t) -> sync.
// Block tile 128(M) x 256(N), BK=32, 256 threads, warp tile 64x64.
// A [M,*] row-major fp16 (lda halves); BT [Ntot][512] row-major fp16.
// C fp32 optional (skip if null); C16 fp16 optional (ld 1024).
// Fused epilogue: ss / colsum / q.ks row-dot.
// ===========================================================================
__global__ __launch_bounds__(256) void gemm16_nn(
    const __half* __restrict__ A, const __half* __restrict__ BT,
    const float* __restrict__ bias, float* __restrict__ C,
    __half* __restrict__ C16,
    int K, int lda, int ldc,
    float* __restrict__ ss_out,
    float* __restrict__ colsum_out,
    const float* __restrict__ ksvec,
    float* __restrict__ qdp_out)
{
    __shared__ unsigned As[128 * 20];   // [m][k2] half2, stride 20 (16 used)
    __shared__ unsigned Bs[256 * 20];   // [n][k2] half2
    __shared__ float epism[4096];
    __shared__ float rsm[8];

    const int tid = threadIdx.x;
    const int lane = tid & 31;
    const int wid = tid >> 5;
    const int gid = lane >> 2, tig = lane & 3;
    const int warp_m = (wid & 1) * 64;
    const int warp_n = (wid >> 1) * 64;
    const int m0 = blockIdx.y * 128;
    const int n0 = blockIdx.x * 256;
    const int T = K >> 5;

    // fill: 16B chunks (8 halves); 4 chunks per 32-half row
    const int frow = tid >> 2;        // 0..63 (+ it*64)
    const int fch  = tid & 3;         // chunk in row

    float acc[4][8][4];
    #pragma unroll
    for (int i = 0; i < 4; i++)
        #pragma unroll
        for (int j = 0; j < 8; j++)
            #pragma unroll
            for (int r = 0; r < 4; r++) acc[i][j][r] = 0.f;

    uint4 pa[2], pb[4];
    #pragma unroll
    for (int it = 0; it < 2; it++)
        pa[it] = *(const uint4*)(A + (size_t)(m0 + frow + it * 64) * lda + fch * 8);
    #pragma unroll
    for (int it = 0; it < 4; it++)
        pb[it] = *(const uint4*)(BT + (size_t)(n0 + frow + it * 64) * 512 + fch * 8);

    for (int t = 0; t < T; t++) {
        #pragma unroll
        for (int it = 0; it < 2; it++)
            *(uint4*)&As[(frow + it * 64) * 20 + fch * 4] = pa[it];
        #pragma unroll
        for (int it = 0; it < 4; it++)
            *(uint4*)&Bs[(frow + it * 64) * 20 + fch * 4] = pb[it];
        __syncthreads();

        if (t + 1 < T) {
            const int k0 = (t + 1) * 32;
            #pragma unroll
            for (int it = 0; it < 2; it++)
                pa[it] = *(const uint4*)(A + (size_t)(m0 + frow + it * 64) * lda + k0 + fch * 8);
            #pragma unroll
            for (int it = 0; it < 4; it++)
                pb[it] = *(const uint4*)(BT + (size_t)(n0 + frow + it * 64) * 512 + k0 + fch * 8);
        }

        #pragma unroll
        for (int kk2 = 0; kk2 < 16; kk2 += 8) {
            unsigned afr[4][4], bfr[8][2];
            #pragma unroll
            for (int i = 0; i < 4; i++) {
                int mm = warp_m + i * 16 + gid;
                afr[i][0] = As[mm * 20 + kk2 + tig];
                afr[i][1] = As[(mm + 8) * 20 + kk2 + tig];
                afr[i][2] = As[mm * 20 + kk2 + tig + 4];
                afr[i][3] = As[(mm + 8) * 20 + kk2 + tig + 4];
            }
            #pragma unroll
            for (int j = 0; j < 8; j++) {
                int nn = warp_n + j * 8 + gid;
                bfr[j][0] = Bs[nn * 20 + kk2 + tig];
                bfr[j][1] = Bs[nn * 20 + kk2 + tig + 4];
            }
            #pragma unroll
            for (int i = 0; i < 4; i++)
                #pragma unroll
                for (int j = 0; j < 8; j++) mma_f16(acc[i][j], afr[i], bfr[j]);
        }
        __syncthreads();
    }

    // ---- epilogue ----
    const bool do_cs = (colsum_out != nullptr);
    const bool do_qd = (qdp_out != nullptr);
    float ss = 0.f;
    float qd[4][2];
    #pragma unroll
    for (int i = 0; i < 4; i++) { qd[i][0] = 0.f; qd[i][1] = 0.f; }

    #pragma unroll
    for (int j = 0; j < 8; j++) {
        int c = n0 + warp_n + j * 8 + tig * 2;
        float bx = bias ? bias[c] : 0.f;
        float by = bias ? bias[c + 1] : 0.f;
        float ks0 = 0.f, ks1 = 0.f;
        if (do_qd) { ks0 = ksvec[c]; ks1 = ksvec[c + 1]; }
        float cs0 = 0.f, cs1 = 0.f;
        #pragma unroll
        for (int i = 0; i < 4; i++) {
            int r = m0 + warp_m + i * 16 + gid;
            float x0 = acc[i][j][0] + bx, x1 = acc[i][j][1] + by;
            float x2 = acc[i][j][2] + bx, x3 = acc[i][j][3] + by;
            if (C) {
                *(float2*)(C + (size_t)r * ldc + c)       = make_float2(x0, x1);
                *(float2*)(C + (size_t)(r + 8) * ldc + c) = make_float2(x2, x3);
            }
            if (C16) {
                *(unsigned*)(C16 + (size_t)r * 1024 + c)       = h2pack(x0, x1);
                *(unsigned*)(C16 + (size_t)(r + 8) * 1024 + c) = h2pack(x2, x3);
            }
            ss += x0 * x0 + x1 * x1 + x2 * x2 + x3 * x3;
            cs0 += x0 + x2; cs1 += x1 + x3;
            qd[i][0] += x0 * ks0 + x1 * ks1;
            qd[i][1] += x2 * ks0 + x3 * ks1;
        }
        if (do_cs) {
            epism[(tid * 8 + j) * 2 + 0] = cs0;
            epism[(tid * 8 + j) * 2 + 1] = cs1;
        }
    }

    if (do_cs) {
        __syncthreads();
        int c = tid;
        int wn = c >> 6, j = (c >> 3) & 7, tg = (c & 7) >> 1, e = c & 1;
        float s = 0.f;
        #pragma unroll
        for (int wm = 0; wm < 2; wm++)
            #pragma unroll
            for (int g = 0; g < 8; g++) {
                int t2 = (2 * wn + wm) * 32 + g * 4 + tg;
                s += epism[(t2 * 8 + j) * 2 + e];
            }
        colsum_out[(size_t)blockIdx.y * 1024 + n0 + c] = s;
    }

    if (do_qd) {
        __syncthreads();
        #pragma unroll
        for (int i = 0; i < 4; i++) {
            epism[(tid * 4 + i) * 2 + 0] = qd[i][0];
            epism[(tid * 4 + i) * 2 + 1] = qd[i][1];
        }
        __syncthreads();
        if (tid < 128) {
            int rl = tid;
            int wm = rl >> 6, rem = rl & 63;
            int i = rem >> 4, hf = (rem >> 3) & 1, g = rem & 7;
            float s = 0.f;
            #pragma unroll
            for (int wn = 0; wn < 4; wn++)
                #pragma unroll
                for (int tg = 0; tg < 4; tg++) {
                    int t2 = (2 * wn + wm) * 32 + g * 4 + tg;
                    s += epism[(t2 * 4 + i) * 2 + hf];
                }
            qdp_out[(size_t)blockIdx.x * 65536u + m0 + rl] = s;
        }
    }

    if (ss_out) {
        float s = block_reduce_sum(ss, rsm);
        if (tid == 0) ss_out[blockIdx.y * gridDim.x + blockIdx.x] = s;
    }
}

// ---------------------------------------------------------------------------
// FP16-operand fused attention GEMM (same pipeline):
//   C[r,c] (+)= 0.5 * inv[r] * ( (A@B)[r,c] * (s*256)  +  65536 * V[r,c] )
// A = q16 head slice (lda 1024 halves); BT = kvsT16 rows of 512 (2^-8 scaled).
// grid (2, 512), N=512, K=512.
// ---------------------------------------------------------------------------
__global__ __launch_bounds__(256) void gemm16_attn(
    const __half* __restrict__ A, const __half* __restrict__ BT,
    const float* __restrict__ Vb, const float* __restrict__ invp,
    const float* __restrict__ scal, float* __restrict__ C, int beta)
{
    __shared__ unsigned As[128 * 20];
    __shared__ unsigned Bs[256 * 20];

    const int tid = threadIdx.x;
    const int lane = tid & 31;
    const int wid = tid >> 5;
    const int gid = lane >> 2, tig = lane & 3;
    const int warp_m = (wid & 1) * 64;
    const int warp_n = (wid >> 1) * 64;
    const int m0 = blockIdx.y * 128;
    const int n0 = blockIdx.x * 256;

    const int frow = tid >> 2;
    const int fch  = tid & 3;

    float acc[4][8][4];
    #pragma unroll
    for (int i = 0; i < 4; i++)
        #pragma unroll
        for (int j = 0; j < 8; j++)
            #pragma unroll
            for (int r = 0; r < 4; r++) acc[i][j][r] = 0.f;

    uint4 pa[2], pb[4];
    #pragma unroll
    for (int it = 0; it < 2; it++)
        pa[it] = *(const uint4*)(A + (size_t)(m0 + frow + it * 64) * 1024 + fch * 8);
    #pragma unroll
    for (int it = 0; it < 4; it++)
        pb[it] = *(const uint4*)(BT + (size_t)(n0 + frow + it * 64) * 512 + fch * 8);

    for (int t = 0; t < 16; t++) {
        #pragma unroll
        for (int it = 0; it < 2; it++)
            *(uint4*)&As[(frow + it * 64) * 20 + fch * 4] = pa[it];
        #pragma unroll
        for (int it = 0; it < 4; it++)
            *(uint4*)&Bs[(frow + it * 64) * 20 + fch * 4] = pb[it];
        __syncthreads();

        if (t + 1 < 16) {
            const int k0 = (t + 1) * 32;
            #pragma unroll
            for (int it = 0; it < 2; it++)
                pa[it] = *(const uint4*)(A + (size_t)(m0 + frow + it * 64) * 1024 + k0 + fch * 8);
            #pragma unroll
            for (int it = 0; it < 4; it++)
                pb[it] = *(const uint4*)(BT + (size_t)(n0 + frow + it * 64) * 512 + k0 + fch * 8);
        }

        #pragma unroll
        for (int kk2 = 0; kk2 < 16; kk2 += 8) {
            unsigned afr[4][4], bfr[8][2];
            #pragma unroll
            for (int i = 0; i < 4; i++) {
                int mm = warp_m + i * 16 + gid;
                afr[i][0] = As[mm * 20 + kk2 + tig];
                afr[i][1] = As[(mm + 8) * 20 + kk2 + tig];
                afr[i][2] = As[mm * 20 + kk2 + tig + 4];
                afr[i][3] = As[(mm + 8) * 20 + kk2 + tig + 4];
            }
            #pragma unroll
            for (int j = 0; j < 8; j++) {
                int nn = warp_n + j * 8 + gid;
                bfr[j][0] = Bs[nn * 20 + kk2 + tig];
                bfr[j][1] = Bs[nn * 20 + kk2 + tig + 4];
            }
            #pragma unroll
            for (int i = 0; i < 4; i++)
                #pragma unroll
                for (int j = 0; j < 8; j++) mma_f16(acc[i][j], afr[i], bfr[j]);
        }
        __syncthreads();
    }

    const float s = rsqrtf(scal[0] * scal[1]) * 256.0f;
    #pragma unroll
    for (int j = 0; j < 8; j++) {
        int c = n0 + warp_n + j * 8 + tig * 2;
        #pragma unroll
        for (int i = 0; i < 4; i++) {
            int r = m0 + warp_m + i * 16 + gid;
            float iv0 = invp[2 * (size_t)r];
            float iv1 = invp[2 * (size_t)(r + 8)];
            float2 va  = *(const float2*)(Vb + (size_t)r * 1024 + c);
            float2 vbv = *(const float2*)(Vb + (size_t)(r + 8) * 1024 + c);
            float x0 = (acc[i][j][0] * s + 65536.f * va.x)  * iv0 * 0.5f;
            float x1 = (acc[i][j][1] * s + 65536.f * va.y)  * iv0 * 0.5f;
            float x2 = (acc[i][j][2] * s + 65536.f * vbv.x) * iv1 * 0.5f;
            float x3 = (acc[i][j][3] * s + 65536.f * vbv.y) * iv1 * 0.5f;
            float* c0 = C + (size_t)r * 1024 + c;
            float* c1 = C + (size_t)(r + 8) * 1024 + c;
            if (beta) {
                float2 o0 = *(float2*)c0, o1 = *(float2*)c1;
                x0 += o0.x; x1 += o0.y; x2 += o1.x; x3 += o1.y;
            }
            *(float2*)c0 = make_float2(x0, x1);
            *(float2*)c1 = make_float2(x2, x3);
        }
    }
}

// ---------------------------------------------------------------------------
// TN GEMM for kvs (tf32 v2, known-good): C[m,d] = sum_l K[l,m]*V[l,d], split-K
// ---------------------------------------------------------------------------
__global__ __launch_bounds__(256) void gemm_tn_kv_v2(
    const float* __restrict__ Kp, const float* __restrict__ Vp,
    float* __restrict__ part)
{
    __shared__ unsigned As[16][264];
    __shared__ unsigned Bs[16][264];

    const int tid = threadIdx.x;
    const int lane = tid & 31;
    const int wid = tid >> 5;
    const int gid = lane >> 2, tig = lane & 3;
    const int warp_m = (wid & 1) * 64;
    const int warp_n = (wid >> 1) * 64;
    const int d0 = blockIdx.x * 256;
    const int m0 = blockIdx.y * 128;
    const int h  = blockIdx.z >> 4;
    const int sp = blockIdx.z & 15;
    const int CH = NPTS / KVSPL;

    const float* Ab = Kp + (size_t)h * 512;
    const float* Bb = Vp + (size_t)h * 512;

    float acc[4][8][4];
    #pragma unroll
    for (int i = 0; i < 4; i++)
        #pragma unroll
        for (int j = 0; j < 8; j++)
            #pragma unroll
            for (int r = 0; r < 4; r++) acc[i][j][r] = 0.f;

    const int lbeg = sp * CH, lend = lbeg + CH;

    float4 pa[2], pb[4];
    #pragma unroll
    for (int it = 0; it < 2; it++) {
        int idx = tid + it * 256;
        int lrow = idx >> 5, mcol4 = (idx & 31) << 2;
        pa[it] = *(const float4*)(Ab + (size_t)(lbeg + lrow) * 1024 + m0 + mcol4);
    }
    #pragma unroll
    for (int it = 0; it < 4; it++) {
        int idx = tid + it * 256;
        int lrow = idx >> 6, dcol4 = (idx & 63) << 2;
        pb[it] = *(const float4*)(Bb + (size_t)(lbeg + lrow) * 1024 + d0 + dcol4);
    }

    for (int l0 = lbeg; l0 < lend; l0 += 16) {
        #pragma unroll
        for (int it = 0; it < 2; it++) {
            int idx = tid + it * 256;
            int lrow = idx >> 5, mcol4 = (idx & 31) << 2;
            *(uint4*)&As[lrow][mcol4] = make_uint4(
                tf32_of(pa[it].x), tf32_of(pa[it].y),
                tf32_of(pa[it].z), tf32_of(pa[it].w));
        }
        #pragma unroll
        for (int it = 0; it < 4; it++) {
            int idx = tid + it * 256;
            int lrow = idx >> 6, dcol4 = (idx & 63) << 2;
            *(uint4*)&Bs[lrow][dcol4] = make_uint4(
                tf32_of(pb[it].x), tf32_of(pb[it].y),
                tf32_of(pb[it].z), tf32_of(pb[it].w));
        }
        __syncthreads();

        if (l0 + 16 < lend) {
            #pragma unroll
            for (int it = 0; it < 2; it++) {
                int idx = tid + it * 256;
                int lrow = idx >> 5, mcol4 = (idx & 31) << 2;
                pa[it] = *(const float4*)(Ab + (size_t)(l0 + 16 + lrow) * 1024 + m0 + mcol4);
            }
            #pragma unroll
            for (int it = 0; it < 4; it++) {
                int idx = tid + it * 256;
                int lrow = idx >> 6, dcol4 = (idx & 63) << 2;
                pb[it] = *(const float4*)(Bb + (size_t)(l0 + 16 + lrow) * 1024 + d0 + dcol4);
            }
        }

        #pragma unroll
        for (int kk = 0; kk < 16; kk += 8) {
            unsigned afr[4][4], bfr[8][2];
            #pragma unroll
            for (int i = 0; i < 4; i++) {
                int mm = warp_m + i * 16 + gid;
                afr[i][0] = As[kk + tig][mm];
                afr[i][1] = As[kk + tig][mm + 8];
                afr[i][2] = As[kk + tig + 4][mm];
                afr[i][3] = As[kk + tig + 4][mm + 8];
            }
            #pragma unroll
            for (int j = 0; j < 8; j++) {
                int nn = warp_n + j * 8 + gid;
                bfr[j][0] = Bs[kk + tig][nn];
                bfr[j][1] = Bs[kk + tig + 4][nn];
            }
            #pragma unroll
            for (int i = 0; i < 4; i++)
                #pragma unroll
                for (int j = 0; j < 8; j++) mma_tf32(acc[i][j], afr[i], bfr[j]);
        }
        __syncthreads();
    }

    float* P = part + (size_t)blockIdx.z * 262144u;
    #pragma unroll
    for (int j = 0; j < 8; j++) {
        int c = d0 + warp_n + j * 8 + tig * 2;
        #pragma unroll
        for (int i = 0; i < 4; i++) {
            int r = m0 + warp_m + i * 16 + gid;
            *(float2*)(P + (size_t)r * 512 + c)       = make_float2(acc[i][j][0], acc[i][j][1]);
            *(float2*)(P + (size_t)(r + 8) * 512 + c) = make_float2(acc[i][j][2], acc[i][j][3]);
        }
    }
}

__global__ void kv_reduce(const float* __restrict__ part, float* __restrict__ kvs) {
    int idx = blockIdx.x * 256 + threadIdx.x;
    int h = idx >> 18;
    int i = idx & 262143;
    const float* p = part + (size_t)(h * KVSPL) * 262144u + i;
    float s = 0.f;
    #pragma unroll
    for (int sp = 0; sp < KVSPL; sp++) s += p[(size_t)sp * 262144u];
    kvs[idx] = s;
}

// ---------------------------------------------------------------------------
// Small reductions / elementwise
// ---------------------------------------------------------------------------
__global__ __launch_bounds__(256) void reduce_to_scalar(
    const float* __restrict__ part, int n, float* __restrict__ out)
{
    __shared__ float sm[8];
    float s = 0.f;
    for (int i = threadIdx.x; i < n; i += 256) s += part[i];
    s = block_reduce_sum(s, sm);
    if (threadIdx.x == 0) *out = s;
}

__global__ __launch_bounds__(256) void ks_reduce512(
    const float* __restrict__ ksp, float* __restrict__ out)
{
    int col = blockIdx.x * 256 + threadIdx.x;
    float s = 0.f;
    for (int by = 0; by < 512; by++) s += ksp[(size_t)by * 1024 + col];
    out[col] = s;
}

__global__ __launch_bounds__(256) void inv_from_qdp(
    const float* __restrict__ qdp, const float* __restrict__ scal,
    float* __restrict__ inv)
{
    int n = blockIdx.x * 256 + threadIdx.x;
    float s = rsqrtf(scal[0] * scal[1]);
    float qd0 = qdp[n] + qdp[65536u + n];
    float qd1 = qdp[2u * 65536u + n] + qdp[3u * 65536u + n];
    inv[2 * n]     = 1.0f / (qd0 * s + 65536.0f);
    inv[2 * n + 1] = 1.0f / (qd1 * s + 65536.0f);
}

// ---------------------------------------------------------------------------
// fc0 epilogue: LayerNorm + ReLU; writes fp32 and fp16 copies
// ---------------------------------------------------------------------------
__global__ __launch_bounds__(256) void ln_relu(
    const float* __restrict__ x, const float* __restrict__ g,
    const float* __restrict__ b, float* __restrict__ out,
    __half* __restrict__ out16)
{
    __shared__ float sm[8];
    int n = blockIdx.x, t = threadIdx.x;
    size_t r = (size_t)n * 512;
    float v0 = x[r + t], v1 = x[r + 256 + t];
    float mu = block_reduce_sum(v0 + v1, sm) * (1.f / 512.f);
    float d0 = v0 - mu, d1 = v1 - mu;
    float var = block_reduce_sum(d0 * d0 + d1 * d1, sm) * (1.f / 512.f);
    float rs = rsqrtf(var + 1e-5f);
    float o0 = fmaxf(d0 * rs * g[t] + b[t], 0.f);
    float o1 = fmaxf(d1 * rs * g[t + 256] + b[t + 256], 0.f);
    out[r + t]       = o0;
    out[r + 256 + t] = o1;
    out16[r + t]       = __float2half(o0);
    out16[r + 256 + t] = __float2half(o1);
}

// ---------------------------------------------------------------------------
// Residual + LayerNorm; optional fp16 copy (prev16 for next layer)
// ---------------------------------------------------------------------------
__global__ __launch_bounds__(256) void combine_res_ln(
    const float* __restrict__ attn, const float* __restrict__ prev,
    const float* __restrict__ g, const float* __restrict__ b,
    float* __restrict__ out, __half* __restrict__ out16)
{
    __shared__ float sm[8];
    int n = blockIdx.x, t = threadIdx.x;
    size_t r1 = (size_t)n * 1024;
    size_t r5 = (size_t)n * 512;
    float val0 = 0.5f * attn[r1 + t]       + 0.5f * prev[r5 + t];
    float val1 = 0.5f * attn[r1 + 256 + t] + 0.5f * prev[r5 + 256 + t];
    float mu = block_reduce_sum(val0 + val1, sm) * (1.f / 512.f);
    float d0 = val0 - mu, d1 = val1 - mu;
    float var = block_reduce_sum(d0 * d0 + d1 * d1, sm) * (1.f / 512.f);
    float rs = rsqrtf(var + 1e-5f);
    float o0 = d0 * rs * g[t] + b[t];
    float o1 = d1 * rs * g[t + 256] + b[t + 256];
    out[r5 + t]       = o0;
    out[r5 + 256 + t] = o1;
    if (out16) {
        out16[r5 + t]       = __float2half(o0);
        out16[r5 + 256 + t] = __float2half(o1);
    }
}

// ---------------------------------------------------------------------------
// Launch
// ---------------------------------------------------------------------------
extern "C" void kernel_launch(void* const* d_in, const int* in_sizes, int n_in,
                              void* d_out, int out_size)
{
    (void)in_sizes; (void)n_in; (void)out_size;
    const float* x     = (const float*)d_in[0];
    const float* fc0_w = (const float*)d_in[1];
    const float* fc0_b = (const float*)d_in[2];
    const float* ln0_g = (const float*)d_in[3];
    const float* ln0_b = (const float*)d_in[4];
    const float* wq    = (const float*)d_in[5];
    const float* bq    = (const float*)d_in[6];
    const float* wk    = (const float*)d_in[7];
    const float* bk    = (const float*)d_in[8];
    const float* wv    = (const float*)d_in[9];
    const float* bv    = (const float*)d_in[10];
    const float* lng   = (const float*)d_in[11];
    const float* lnb   = (const float*)d_in[12];
    float* out = (float*)d_out;

    float *qk, *v, *hbuf, *kvp, *kvs, *ksp, *ks, *red, *scal, *qdp, *inv;
    __half *kvsT16, *wt16, *x16, *a16, *q16;
    cudaGetSymbolAddress((void**)&qk,     g_qk);
    cudaGetSymbolAddress((void**)&v,      g_v);
    cudaGetSymbolAddress((void**)&hbuf,   g_h);
    cudaGetSymbolAddress((void**)&kvp,    g_kvp);
    cudaGetSymbolAddress((void**)&kvs,    g_kvs);
    cudaGetSymbolAddress((void**)&kvsT16, g_kvsT16);
    cudaGetSymbolAddress((void**)&wt16,   g_wt16);
    cudaGetSymbolAddress((void**)&x16,    g_x16);
    cudaGetSymbolAddress((void**)&a16,    g_a16);
    cudaGetSymbolAddress((void**)&q16,    g_q16);
    cudaGetSymbolAddress((void**)&ksp,    g_ksp);
    cudaGetSymbolAddress((void**)&ks,     g_ks);
    cudaGetSymbolAddress((void**)&red,    g_red);
    cudaGetSymbolAddress((void**)&scal,   g_scal);
    cudaGetSymbolAddress((void**)&qdp,    g_qdp);
    cudaGetSymbolAddress((void**)&inv,    g_inv);

    dim3 thr(256);
    dim3 tb(32, 8);

    // launch order tuned so ncu -s 5 lands on a projection GEMM (#5)
    cvt_f2h<<<32768, thr>>>(x, x16, 65536 * 512 / 4);                    // 0
    transpose_h<<<dim3(16, 16), tb>>>(fc0_w, 512, 512, wt16, 1.0f);      // 1
    gemm16_nn<<<dim3(2, 512), thr>>>(x16, wt16, fc0_b, v, nullptr,       // 2
                                     512, 512, 512,
                                     nullptr, nullptr, nullptr, nullptr);
    ln_relu<<<NPTS, thr>>>(v, ln0_g, ln0_b, hbuf, a16);                  // 3

    for (int L = 0; L < 2; L++) {
        const float*  prev   = L ? out : hbuf;
        const __half* prev16 = a16;
        float* lout = out;
        __half* WQT = wt16 + (size_t)(1 + 3 * L) * 524288u;
        __half* WKT = wt16 + (size_t)(2 + 3 * L) * 524288u;
        __half* WVT = wt16 + (size_t)(3 + 3 * L) * 524288u;
        const float* BQ  = bq + (size_t)L * 1024;
        const float* BKb = bk + (size_t)L * 1024;
        const float* BV  = bv + (size_t)L * 1024;

        transpose_h<<<dim3(32, 16), tb>>>(wv + (size_t)L * 524288u, 512, 1024,
                                          WVT, 1.0f);                    // 4 (L0)
        // V projection                                                  // 5 (L0) <- profiled
        gemm16_nn<<<dim3(4, 512), thr>>>(prev16, WVT, BV, v, nullptr,
                                         512, 512, 1024,
                                         nullptr, nullptr, nullptr, nullptr);
        transpose_h<<<dim3(32, 16), tb>>>(wk + (size_t)L * 524288u, 512, 1024,
                                          WKT, 1.0f);
        // K projection (+ ss, + colsum); fp32 K kept for kv gemm
        gemm16_nn<<<dim3(4, 512), thr>>>(prev16, WKT, BKb, qk, nullptr,
                                         512, 512, 1024,
                                         red + 4096, ksp, nullptr, nullptr);
        reduce_to_scalar<<<1, thr>>>(red + 4096, 2048, scal + 1);
        ks_reduce512<<<4, thr>>>(ksp, ks);

        // kvs = K^T V per head (split-K, tf32); transpose+scale to fp16
        gemm_tn_kv_v2<<<dim3(2, 4, 32), thr>>>(qk, v, kvp);
        kv_reduce<<<2048, thr>>>(kvp, kvs);
        transpose_h<<<dim3(16, 16), tb>>>(kvs, 512, 512, kvsT16, 0.00390625f);
        transpose_h<<<dim3(16, 16), tb>>>(kvs + 262144u, 512, 512,
                                          kvsT16 + 262144u, 0.00390625f);

        // Q projection: fp16-only output (+ ss, + q.ks partials)
        transpose_h<<<dim3(32, 16), tb>>>(wq + (size_t)L * 524288u, 512, 1024,
                                          WQT, 1.0f);
        gemm16_nn<<<dim3(4, 512), thr>>>(prev16, WQT, BQ, nullptr, q16,
                                         512, 512, 1024,
                                         red, nullptr, ks, qdp);
        reduce_to_scalar<<<1, thr>>>(red, 2048, scal + 0);
        inv_from_qdp<<<256, thr>>>(qdp, scal, inv);

        // fused Q@kvs + attention combine; attn aliases V's head-0 half
        gemm16_attn<<<dim3(2, 512), thr>>>(q16, kvsT16, v, inv, scal, v, 0);
        gemm16_attn<<<dim3(2, 512), thr>>>(q16 + 512, kvsT16 + 262144u,
                                           v + 512, inv + 1, scal, v, 1);

        // residual + LN (writes prev16 for next layer when L==0)
        combine_res_ln<<<NPTS, thr>>>(v, prev,
                                      lng + (size_t)L * 512, lnb + (size_t)L * 512,
                                      lout, L == 0 ? a16 : nullptr);
    }
}

// round 17
// speedup vs baseline: 2.0703x; 1.0435x over previous
#include <cuda_runtime.h>
#include <cuda_bf16.h>
#include <cuda_fp16.h>
#include <cstdint>
#include <cstddef>

// ---------------------------------------------------------------------------
// Problem constants
// ---------------------------------------------------------------------------
static const int NPTS  = 65536;
static const int HID   = 512;
static const int HH    = 1024;
static const int NSPL  = 32;     // split-K per head for kv gemm

// ---------------------------------------------------------------------------
// Scratch (device globals; no allocation allowed)
// ---------------------------------------------------------------------------
__device__ float  g_v   [65536u * 1024u];     // V fp32; head-0 half later holds attn
__device__ float  g_h   [65536u * 512u];      // fc0 output fp32 (residual)
__device__ float  g_kvp [64u * 512u * 512u];  // split-K partials (2 heads * 32)
__device__ float  g_kvs [2u * 512u * 512u];   // K^T V per head [m][d]
__device__ __half g_kvsT16[2u * 262144u];     // [d][m] fp16, scaled 2^-8
__device__ __half g_wt16[7u * 524288u];       // transposed fp16 weights
__device__ __half g_x16 [65536u * 512u];      // x in fp16
__device__ __half g_a16 [65536u * 512u];      // prev activations fp16
__device__ __half g_q16 [65536u * 1024u];     // K fp16 (temp), then Q fp16
__device__ __half g_kT16[1024u * 65536u];     // K^T fp16 [feature][l]
__device__ __half g_vT16[1024u * 65536u];     // V^T fp16 [feature][l]
__device__ float  g_ksp [512u * 1024u];
__device__ float  g_ks  [1024u];
__device__ float  g_red [8192u];
__device__ float  g_scal[2u];
__device__ float  g_qdp [4u * 65536u];
__device__ float  g_inv [2u * 65536u];

// ---------------------------------------------------------------------------
// Helpers
// ---------------------------------------------------------------------------
__device__ __forceinline__ unsigned h2pack(float lo, float hi) {
    unsigned u;
    asm("{ .reg .f16 l, h; cvt.rn.f16.f32 l, %1; cvt.rn.f16.f32 h, %2; "
        "mov.b32 %0, {l, h}; }" : "=r"(u) : "f"(lo), "f"(hi));
    return u;
}

__device__ __forceinline__ void mma_f16(float c[4], const unsigned a[4],
                                        const unsigned b[2]) {
    asm volatile(
        "mma.sync.aligned.m16n8k16.row.col.f32.f16.f16.f32 "
        "{%0,%1,%2,%3},{%4,%5,%6,%7},{%8,%9},{%0,%1,%2,%3};\n"
        : "+f"(c[0]), "+f"(c[1]), "+f"(c[2]), "+f"(c[3])
        : "r"(a[0]), "r"(a[1]), "r"(a[2]), "r"(a[3]), "r"(b[0]), "r"(b[1]));
}

__device__ __forceinline__ float block_reduce_sum(float v, float* sm) {
    int tid = threadIdx.x;
    int lane = tid & 31, wid = tid >> 5;
    #pragma unroll
    for (int o = 16; o > 0; o >>= 1) v += __shfl_down_sync(0xffffffffu, v, o);
    __syncthreads();
    if (lane == 0) sm[wid] = v;
    __syncthreads();
    if (tid == 0) {
        float s = 0.f;
        #pragma unroll
        for (int i = 0; i < 8; i++) s += sm[i];
        sm[0] = s;
    }
    __syncthreads();
    return sm[0];
}

// ---------------------------------------------------------------------------
// fp32 -> fp16 bulk convert
// ---------------------------------------------------------------------------
__global__ __launch_bounds__(256) void cvt_f2h(
    const float* __restrict__ in, __half* __restrict__ out, int n4)
{
    int i = blockIdx.x * 256 + threadIdx.x;
    if (i < n4) {
        float4 v = ((const float4*)in)[i];
        uint2 u;
        u.x = h2pack(v.x, v.y);
        u.y = h2pack(v.z, v.w);
        ((uint2*)out)[i] = u;
    }
}

// ---------------------------------------------------------------------------
// Tiled transpose fp32 -> fp16 with scale: out[C][R] = (half)(scale * in^T)
// block (32,8), grid (C/32, R/32)
// ---------------------------------------------------------------------------
__global__ void transpose_h(const float* __restrict__ in, int R, int C,
                            __half* __restrict__ out, float scale)
{
    __shared__ float t[32][33];
    int c0 = blockIdx.x * 32, r0 = blockIdx.y * 32;
    int x = threadIdx.x, y = threadIdx.y;
    #pragma unroll
    for (int i = 0; i < 32; i += 8)
        t[y + i][x] = in[(size_t)(r0 + y + i) * C + c0 + x];
    __syncthreads();
    #pragma unroll
    for (int i = 0; i < 32; i += 8)
        out[(size_t)(c0 + y + i) * R + r0 + x] = __float2half(t[x][y + i] * scale);
}

// ---------------------------------------------------------------------------
// Tiled transpose fp16 -> fp16: out[C][R] = in[R][C]^T
// 64x64 tile, block (32,8), grid (C/64, R/64); half2 global accesses
// ---------------------------------------------------------------------------
__global__ void transpose_hh(const __half* __restrict__ in, int R, int C,
                             __half* __restrict__ out)
{
    __shared__ __half t[64][66];
    int c0 = blockIdx.x * 64, r0 = blockIdx.y * 64;
    int x = threadIdx.x, y = threadIdx.y;
    #pragma unroll
    for (int i = 0; i < 8; i++) {
        int r = y + i * 8;
        *(half2*)&t[r][2 * x] =
            *(const half2*)(in + (size_t)(r0 + r) * C + c0 + 2 * x);
    }
    __syncthreads();
    #pragma unroll
    for (int i = 0; i < 8; i++) {
        int col = y + i * 8;
        half2 vv;
        vv.x = t[2 * x][col];
        vv.y = t[2 * x + 1][col];
        *(half2*)(out + (size_t)(c0 + col) * R + r0 + 2 * x) = vv;
    }
}

// ===========================================================================
// FP16-operand GEMM core (register-prefetch pipeline, no cvt in fill):
// per tile: STS(t) -> sync -> LDG(t+1) -> MMA(t) -> sync.
// Block tile 128(M) x 256(N), BK=32, 256 threads, warp tile 64x64.
// A [M,*] row-major fp16 (lda halves); BT [Ntot][512] row-major fp16.
// C fp32 optional; C16 fp16 optional (ld 1024).
// Fused epilogue: ss / colsum / q.ks row-dot.
// ===========================================================================
__global__ __launch_bounds__(256) void gemm16_nn(
    const __half* __restrict__ A, const __half* __restrict__ BT,
    const float* __restrict__ bias, float* __restrict__ C,
    __half* __restrict__ C16,
    int K, int lda, int ldc,
    float* __restrict__ ss_out,
    float* __restrict__ colsum_out,
    const float* __restrict__ ksvec,
    float* __restrict__ qdp_out)
{
    __shared__ unsigned As[128 * 20];
    __shared__ unsigned Bs[256 * 20];
    __shared__ float epism[4096];
    __shared__ float rsm[8];

    const int tid = threadIdx.x;
    const int lane = tid & 31;
    const int wid = tid >> 5;
    const int gid = lane >> 2, tig = lane & 3;
    const int warp_m = (wid & 1) * 64;
    const int warp_n = (wid >> 1) * 64;
    const int m0 = blockIdx.y * 128;
    const int n0 = blockIdx.x * 256;
    const int T = K >> 5;

    const int frow = tid >> 2;
    const int fch  = tid & 3;

    float acc[4][8][4];
    #pragma unroll
    for (int i = 0; i < 4; i++)
        #pragma unroll
        for (int j = 0; j < 8; j++)
            #pragma unroll
            for (int r = 0; r < 4; r++) acc[i][j][r] = 0.f;

    uint4 pa[2], pb[4];
    #pragma unroll
    for (int it = 0; it < 2; it++)
        pa[it] = *(const uint4*)(A + (size_t)(m0 + frow + it * 64) * lda + fch * 8);
    #pragma unroll
    for (int it = 0; it < 4; it++)
        pb[it] = *(const uint4*)(BT + (size_t)(n0 + frow + it * 64) * 512 + fch * 8);

    for (int t = 0; t < T; t++) {
        #pragma unroll
        for (int it = 0; it < 2; it++)
            *(uint4*)&As[(frow + it * 64) * 20 + fch * 4] = pa[it];
        #pragma unroll
        for (int it = 0; it < 4; it++)
            *(uint4*)&Bs[(frow + it * 64) * 20 + fch * 4] = pb[it];
        __syncthreads();

        if (t + 1 < T) {
            const int k0 = (t + 1) * 32;
            #pragma unroll
            for (int it = 0; it < 2; it++)
                pa[it] = *(const uint4*)(A + (size_t)(m0 + frow + it * 64) * lda + k0 + fch * 8);
            #pragma unroll
            for (int it = 0; it < 4; it++)
                pb[it] = *(const uint4*)(BT + (size_t)(n0 + frow + it * 64) * 512 + k0 + fch * 8);
        }

        #pragma unroll
        for (int kk2 = 0; kk2 < 16; kk2 += 8) {
            unsigned afr[4][4], bfr[8][2];
            #pragma unroll
            for (int i = 0; i < 4; i++) {
                int mm = warp_m + i * 16 + gid;
                afr[i][0] = As[mm * 20 + kk2 + tig];
                afr[i][1] = As[(mm + 8) * 20 + kk2 + tig];
                afr[i][2] = As[mm * 20 + kk2 + tig + 4];
                afr[i][3] = As[(mm + 8) * 20 + kk2 + tig + 4];
            }
            #pragma unroll
            for (int j = 0; j < 8; j++) {
                int nn = warp_n + j * 8 + gid;
                bfr[j][0] = Bs[nn * 20 + kk2 + tig];
                bfr[j][1] = Bs[nn * 20 + kk2 + tig + 4];
            }
            #pragma unroll
            for (int i = 0; i < 4; i++)
                #pragma unroll
                for (int j = 0; j < 8; j++) mma_f16(acc[i][j], afr[i], bfr[j]);
        }
        __syncthreads();
    }

    const bool do_cs = (colsum_out != nullptr);
    const bool do_qd = (qdp_out != nullptr);
    float ss = 0.f;
    float qd[4][2];
    #pragma unroll
    for (int i = 0; i < 4; i++) { qd[i][0] = 0.f; qd[i][1] = 0.f; }

    #pragma unroll
    for (int j = 0; j < 8; j++) {
        int c = n0 + warp_n + j * 8 + tig * 2;
        float bx = bias ? bias[c] : 0.f;
        float by = bias ? bias[c + 1] : 0.f;
        float ks0 = 0.f, ks1 = 0.f;
        if (do_qd) { ks0 = ksvec[c]; ks1 = ksvec[c + 1]; }
        float cs0 = 0.f, cs1 = 0.f;
        #pragma unroll
        for (int i = 0; i < 4; i++) {
            int r = m0 + warp_m + i * 16 + gid;
            float x0 = acc[i][j][0] + bx, x1 = acc[i][j][1] + by;
            float x2 = acc[i][j][2] + bx, x3 = acc[i][j][3] + by;
            if (C) {
                *(float2*)(C + (size_t)r * ldc + c)       = make_float2(x0, x1);
                *(float2*)(C + (size_t)(r + 8) * ldc + c) = make_float2(x2, x3);
            }
            if (C16) {
                *(unsigned*)(C16 + (size_t)r * 1024 + c)       = h2pack(x0, x1);
                *(unsigned*)(C16 + (size_t)(r + 8) * 1024 + c) = h2pack(x2, x3);
            }
            ss += x0 * x0 + x1 * x1 + x2 * x2 + x3 * x3;
            cs0 += x0 + x2; cs1 += x1 + x3;
            qd[i][0] += x0 * ks0 + x1 * ks1;
            qd[i][1] += x2 * ks0 + x3 * ks1;
        }
        if (do_cs) {
            epism[(tid * 8 + j) * 2 + 0] = cs0;
            epism[(tid * 8 + j) * 2 + 1] = cs1;
        }
    }

    if (do_cs) {
        __syncthreads();
        int c = tid;
        int wn = c >> 6, j = (c >> 3) & 7, tg = (c & 7) >> 1, e = c & 1;
        float s = 0.f;
        #pragma unroll
        for (int wm = 0; wm < 2; wm++)
            #pragma unroll
            for (int g = 0; g < 8; g++) {
                int t2 = (2 * wn + wm) * 32 + g * 4 + tg;
                s += epism[(t2 * 8 + j) * 2 + e];
            }
        colsum_out[(size_t)blockIdx.y * 1024 + n0 + c] = s;
    }

    if (do_qd) {
        __syncthreads();
        #pragma unroll
        for (int i = 0; i < 4; i++) {
            epism[(tid * 4 + i) * 2 + 0] = qd[i][0];
            epism[(tid * 4 + i) * 2 + 1] = qd[i][1];
        }
        __syncthreads();
        if (tid < 128) {
            int rl = tid;
            int wm = rl >> 6, rem = rl & 63;
            int i = rem >> 4, hf = (rem >> 3) & 1, g = rem & 7;
            float s = 0.f;
            #pragma unroll
            for (int wn = 0; wn < 4; wn++)
                #pragma unroll
                for (int tg = 0; tg < 4; tg++) {
                    int t2 = (2 * wn + wm) * 32 + g * 4 + tg;
                    s += epism[(t2 * 4 + i) * 2 + hf];
                }
            qdp_out[(size_t)blockIdx.x * 65536u + m0 + rl] = s;
        }
    }

    if (ss_out) {
        float s = block_reduce_sum(ss, rsm);
        if (tid == 0) ss_out[blockIdx.y * gridDim.x + blockIdx.x] = s;
    }
}

// ---------------------------------------------------------------------------
// FP16 split-K kv GEMM: P[m,d] = sum_{l in chunk} KT[m][l] * VT[d][l]
// KT/VT [1024][65536] fp16 row-major.  grid (2, 4, z = h*NSPL + sp).
// Same core as gemm16_nn; chunk = 65536/NSPL, T = chunk/32.
// ---------------------------------------------------------------------------
__global__ __launch_bounds__(256) void gemm16_kv(
    const __half* __restrict__ KT, const __half* __restrict__ VT,
    float* __restrict__ part)
{
    __shared__ unsigned As[128 * 20];
    __shared__ unsigned Bs[256 * 20];

    const int tid = threadIdx.x;
    const int lane = tid & 31;
    const int wid = tid >> 5;
    const int gid = lane >> 2, tig = lane & 3;
    const int warp_m = (wid & 1) * 64;
    const int warp_n = (wid >> 1) * 64;
    const int n0 = blockIdx.x * 256;          // d tile
    const int m0 = blockIdx.y * 128;          // m tile
    const int h  = blockIdx.z >> 5;
    const int sp = blockIdx.z & 31;
    const int CH = NPTS / NSPL;               // 2048
    const int T  = CH >> 5;                   // 64
    const int lbeg = sp * CH;

    const __half* Ab = KT + (size_t)h * 512 * 65536u + lbeg;
    const __half* Bb = VT + (size_t)h * 512 * 65536u + lbeg;

    const int frow = tid >> 2;
    const int fch  = tid & 3;

    float acc[4][8][4];
    #pragma unroll
    for (int i = 0; i < 4; i++)
        #pragma unroll
        for (int j = 0; j < 8; j++)
            #pragma unroll
            for (int r = 0; r < 4; r++) acc[i][j][r] = 0.f;

    uint4 pa[2], pb[4];
    #pragma unroll
    for (int it = 0; it < 2; it++)
        pa[it] = *(const uint4*)(Ab + (size_t)(m0 + frow + it * 64) * 65536u + fch * 8);
    #pragma unroll
    for (int it = 0; it < 4; it++)
        pb[it] = *(const uint4*)(Bb + (size_t)(n0 + frow + it * 64) * 65536u + fch * 8);

    for (int t = 0; t < T; t++) {
        #pragma unroll
        for (int it = 0; it < 2; it++)
            *(uint4*)&As[(frow + it * 64) * 20 + fch * 4] = pa[it];
        #pragma unroll
        for (int it = 0; it < 4; it++)
            *(uint4*)&Bs[(frow + it * 64) * 20 + fch * 4] = pb[it];
        __syncthreads();

        if (t + 1 < T) {
            const int k0 = (t + 1) * 32;
            #pragma unroll
            for (int it = 0; it < 2; it++)
                pa[it] = *(const uint4*)(Ab + (size_t)(m0 + frow + it * 64) * 65536u + k0 + fch * 8);
            #pragma unroll
            for (int it = 0; it < 4; it++)
                pb[it] = *(const uint4*)(Bb + (size_t)(n0 + frow + it * 64) * 65536u + k0 + fch * 8);
        }

        #pragma unroll
        for (int kk2 = 0; kk2 < 16; kk2 += 8) {
            unsigned afr[4][4], bfr[8][2];
            #pragma unroll
            for (int i = 0; i < 4; i++) {
                int mm = warp_m + i * 16 + gid;
                afr[i][0] = As[mm * 20 + kk2 + tig];
                afr[i][1] = As[(mm + 8) * 20 + kk2 + tig];
                afr[i][2] = As[mm * 20 + kk2 + tig + 4];
                afr[i][3] = As[(mm + 8) * 20 + kk2 + tig + 4];
            }
            #pragma unroll
            for (int j = 0; j < 8; j++) {
                int nn = warp_n + j * 8 + gid;
                bfr[j][0] = Bs[nn * 20 + kk2 + tig];
                bfr[j][1] = Bs[nn * 20 + kk2 + tig + 4];
            }
            #pragma unroll
            for (int i = 0; i < 4; i++)
                #pragma unroll
                for (int j = 0; j < 8; j++) mma_f16(acc[i][j], afr[i], bfr[j]);
        }
        __syncthreads();
    }

    float* P = part + (size_t)blockIdx.z * 262144u;
    #pragma unroll
    for (int j = 0; j < 8; j++) {
        int c = n0 + warp_n + j * 8 + tig * 2;
        #pragma unroll
        for (int i = 0; i < 4; i++) {
            int r = m0 + warp_m + i * 16 + gid;
            *(float2*)(P + (size_t)r * 512 + c)       = make_float2(acc[i][j][0], acc[i][j][1]);
            *(float2*)(P + (size_t)(r + 8) * 512 + c) = make_float2(acc[i][j][2], acc[i][j][3]);
        }
    }
}

// ---------------------------------------------------------------------------
// FP16 fused attention GEMM (register-prefetch pipeline):
//   C[r,c] (+)= 0.5 * inv[r] * ( (A@B)[r,c] * (s*256)  +  65536 * V[r,c] )
// ---------------------------------------------------------------------------
__global__ __launch_bounds__(256) void gemm16_attn(
    const __half* __restrict__ A, const __half* __restrict__ BT,
    const float* __restrict__ Vb, const float* __restrict__ invp,
    const float* __restrict__ scal, float* __restrict__ C, int beta)
{
    __shared__ unsigned As[128 * 20];
    __shared__ unsigned Bs[256 * 20];

    const int tid = threadIdx.x;
    const int lane = tid & 31;
    const int wid = tid >> 5;
    const int gid = lane >> 2, tig = lane & 3;
    const int warp_m = (wid & 1) * 64;
    const int warp_n = (wid >> 1) * 64;
    const int m0 = blockIdx.y * 128;
    const int n0 = blockIdx.x * 256;

    const int frow = tid >> 2;
    const int fch  = tid & 3;

    float acc[4][8][4];
    #pragma unroll
    for (int i = 0; i < 4; i++)
        #pragma unroll
        for (int j = 0; j < 8; j++)
            #pragma unroll
            for (int r = 0; r < 4; r++) acc[i][j][r] = 0.f;

    uint4 pa[2], pb[4];
    #pragma unroll
    for (int it = 0; it < 2; it++)
        pa[it] = *(const uint4*)(A + (size_t)(m0 + frow + it * 64) * 1024 + fch * 8);
    #pragma unroll
    for (int it = 0; it < 4; it++)
        pb[it] = *(const uint4*)(BT + (size_t)(n0 + frow + it * 64) * 512 + fch * 8);

    for (int t = 0; t < 16; t++) {
        #pragma unroll
        for (int it = 0; it < 2; it++)
            *(uint4*)&As[(frow + it * 64) * 20 + fch * 4] = pa[it];
        #pragma unroll
        for (int it = 0; it < 4; it++)
            *(uint4*)&Bs[(frow + it * 64) * 20 + fch * 4] = pb[it];
        __syncthreads();

        if (t + 1 < 16) {
            const int k0 = (t + 1) * 32;
            #pragma unroll
            for (int it = 0; it < 2; it++)
                pa[it] = *(const uint4*)(A + (size_t)(m0 + frow + it * 64) * 1024 + k0 + fch * 8);
            #pragma unroll
            for (int it = 0; it < 4; it++)
                pb[it] = *(const uint4*)(BT + (size_t)(n0 + frow + it * 64) * 512 + k0 + fch * 8);
        }

        #pragma unroll
        for (int kk2 = 0; kk2 < 16; kk2 += 8) {
            unsigned afr[4][4], bfr[8][2];
            #pragma unroll
            for (int i = 0; i < 4; i++) {
                int mm = warp_m + i * 16 + gid;
                afr[i][0] = As[mm * 20 + kk2 + tig];
                afr[i][1] = As[(mm + 8) * 20 + kk2 + tig];
                afr[i][2] = As[mm * 20 + kk2 + tig + 4];
                afr[i][3] = As[(mm + 8) * 20 + kk2 + tig + 4];
            }
            #pragma unroll
            for (int j = 0; j < 8; j++) {
                int nn = warp_n + j * 8 + gid;
                bfr[j][0] = Bs[nn * 20 + kk2 + tig];
                bfr[j][1] = Bs[nn * 20 + kk2 + tig + 4];
            }
            #pragma unroll
            for (int i = 0; i < 4; i++)
                #pragma unroll
                for (int j = 0; j < 8; j++) mma_f16(acc[i][j], afr[i], bfr[j]);
        }
        __syncthreads();
    }

    const float s = rsqrtf(scal[0] * scal[1]) * 256.0f;
    #pragma unroll
    for (int j = 0; j < 8; j++) {
        int c = n0 + warp_n + j * 8 + tig * 2;
        #pragma unroll
        for (int i = 0; i < 4; i++) {
            int r = m0 + warp_m + i * 16 + gid;
            float iv0 = invp[2 * (size_t)r];
            float iv1 = invp[2 * (size_t)(r + 8)];
            float2 va  = *(const float2*)(Vb + (size_t)r * 1024 + c);
            float2 vbv = *(const float2*)(Vb + (size_t)(r + 8) * 1024 + c);
            float x0 = (acc[i][j][0] * s + 65536.f * va.x)  * iv0 * 0.5f;
            float x1 = (acc[i][j][1] * s + 65536.f * va.y)  * iv0 * 0.5f;
            float x2 = (acc[i][j][2] * s + 65536.f * vbv.x) * iv1 * 0.5f;
            float x3 = (acc[i][j][3] * s + 65536.f * vbv.y) * iv1 * 0.5f;
            float* c0 = C + (size_t)r * 1024 + c;
            float* c1 = C + (size_t)(r + 8) * 1024 + c;
            if (beta) {
                float2 o0 = *(float2*)c0, o1 = *(float2*)c1;
                x0 += o0.x; x1 += o0.y; x2 += o1.x; x3 += o1.y;
            }
            *(float2*)c0 = make_float2(x0, x1);
            *(float2*)c1 = make_float2(x2, x3);
        }
    }
}

__global__ void kv_reduce(const float* __restrict__ part, float* __restrict__ kvs) {
    int idx = blockIdx.x * 256 + threadIdx.x;          // 0..524287
    int h = idx >> 18;
    int i = idx & 262143;
    const float* p = part + (size_t)(h * NSPL) * 262144u + i;
    float s = 0.f;
    #pragma unroll
    for (int sp = 0; sp < NSPL; sp++) s += p[(size_t)sp * 262144u];
    kvs[idx] = s;
}

// ---------------------------------------------------------------------------
// Small reductions / elementwise
// ---------------------------------------------------------------------------
__global__ __launch_bounds__(256) void reduce_to_scalar(
    const float* __restrict__ part, int n, float* __restrict__ out)
{
    __shared__ float sm[8];
    float s = 0.f;
    for (int i = threadIdx.x; i < n; i += 256) s += part[i];
    s = block_reduce_sum(s, sm);
    if (threadIdx.x == 0) *out = s;
}

__global__ __launch_bounds__(256) void ks_reduce512(
    const float* __restrict__ ksp, float* __restrict__ out)
{
    int col = blockIdx.x * 256 + threadIdx.x;
    float s = 0.f;
    for (int by = 0; by < 512; by++) s += ksp[(size_t)by * 1024 + col];
    out[col] = s;
}

__global__ __launch_bounds__(256) void inv_from_qdp(
    const float* __restrict__ qdp, const float* __restrict__ scal,
    float* __restrict__ inv)
{
    int n = blockIdx.x * 256 + threadIdx.x;
    float s = rsqrtf(scal[0] * scal[1]);
    float qd0 = qdp[n] + qdp[65536u + n];
    float qd1 = qdp[2u * 65536u + n] + qdp[3u * 65536u + n];
    inv[2 * n]     = 1.0f / (qd0 * s + 65536.0f);
    inv[2 * n + 1] = 1.0f / (qd1 * s + 65536.0f);
}

__global__ __launch_bounds__(256) void ln_relu(
    const float* __restrict__ x, const float* __restrict__ g,
    const float* __restrict__ b, float* __restrict__ out,
    __half* __restrict__ out16)
{
    __shared__ float sm[8];
    int n = blockIdx.x, t = threadIdx.x;
    size_t r = (size_t)n * 512;
    float v0 = x[r + t], v1 = x[r + 256 + t];
    float mu = block_reduce_sum(v0 + v1, sm) * (1.f / 512.f);
    float d0 = v0 - mu, d1 = v1 - mu;
    float var = block_reduce_sum(d0 * d0 + d1 * d1, sm) * (1.f / 512.f);
    float rs = rsqrtf(var + 1e-5f);
    float o0 = fmaxf(d0 * rs * g[t] + b[t], 0.f);
    float o1 = fmaxf(d1 * rs * g[t + 256] + b[t + 256], 0.f);
    out[r + t]       = o0;
    out[r + 256 + t] = o1;
    out16[r + t]       = __float2half(o0);
    out16[r + 256 + t] = __float2half(o1);
}

__global__ __launch_bounds__(256) void combine_res_ln(
    const float* __restrict__ attn, const float* __restrict__ prev,
    const float* __restrict__ g, const float* __restrict__ b,
    float* __restrict__ out, __half* __restrict__ out16)
{
    __shared__ float sm[8];
    int n = blockIdx.x, t = threadIdx.x;
    size_t r1 = (size_t)n * 1024;
    size_t r5 = (size_t)n * 512;
    float val0 = 0.5f * attn[r1 + t]       + 0.5f * prev[r5 + t];
    float val1 = 0.5f * attn[r1 + 256 + t] + 0.5f * prev[r5 + 256 + t];
    float mu = block_reduce_sum(val0 + val1, sm) * (1.f / 512.f);
    float d0 = val0 - mu, d1 = val1 - mu;
    float var = block_reduce_sum(d0 * d0 + d1 * d1, sm) * (1.f / 512.f);
    float rs = rsqrtf(var + 1e-5f);
    float o0 = d0 * rs * g[t] + b[t];
    float o1 = d1 * rs * g[t + 256] + b[t + 256];
    out[r5 + t]       = o0;
    out[r5 + 256 + t] = o1;
    if (out16) {
        out16[r5 + t]       = __float2half(o0);
        out16[r5 + 256 + t] = __float2half(o1);
    }
}

// ---------------------------------------------------------------------------
// Launch
// ---------------------------------------------------------------------------
extern "C" void kernel_launch(void* const* d_in, const int* in_sizes, int n_in,
                              void* d_out, int out_size)
{
    (void)in_sizes; (void)n_in; (void)out_size;
    const float* x     = (const float*)d_in[0];
    const float* fc0_w = (const float*)d_in[1];
    const float* fc0_b = (const float*)d_in[2];
    const float* ln0_g = (const float*)d_in[3];
    const float* ln0_b = (const float*)d_in[4];
    const float* wq    = (const float*)d_in[5];
    const float* bq    = (const float*)d_in[6];
    const float* wk    = (const float*)d_in[7];
    const float* bk    = (const float*)d_in[8];
    const float* wv    = (const float*)d_in[9];
    const float* bv    = (const float*)d_in[10];
    const float* lng   = (const float*)d_in[11];
    const float* lnb   = (const float*)d_in[12];
    float* out = (float*)d_out;

    float *v, *hbuf, *kvp, *kvs, *ksp, *ks, *red, *scal, *qdp, *inv;
    __half *kvsT16, *wt16, *x16, *a16, *q16, *kT16, *vT16;
    cudaGetSymbolAddress((void**)&v,      g_v);
    cudaGetSymbolAddress((void**)&hbuf,   g_h);
    cudaGetSymbolAddress((void**)&kvp,    g_kvp);
    cudaGetSymbolAddress((void**)&kvs,    g_kvs);
    cudaGetSymbolAddress((void**)&kvsT16, g_kvsT16);
    cudaGetSymbolAddress((void**)&wt16,   g_wt16);
    cudaGetSymbolAddress((void**)&x16,    g_x16);
    cudaGetSymbolAddress((void**)&a16,    g_a16);
    cudaGetSymbolAddress((void**)&q16,    g_q16);
    cudaGetSymbolAddress((void**)&kT16,   g_kT16);
    cudaGetSymbolAddress((void**)&vT16,   g_vT16);
    cudaGetSymbolAddress((void**)&ksp,    g_ksp);
    cudaGetSymbolAddress((void**)&ks,     g_ks);
    cudaGetSymbolAddress((void**)&red,    g_red);
    cudaGetSymbolAddress((void**)&scal,   g_scal);
    cudaGetSymbolAddress((void**)&qdp,    g_qdp);
    cudaGetSymbolAddress((void**)&inv,    g_inv);

    dim3 thr(256);
    dim3 tb(32, 8);

    cvt_f2h<<<32768, thr>>>(x, x16, 65536 * 512 / 4);
    transpose_h<<<dim3(16, 16), tb>>>(fc0_w, 512, 512, wt16, 1.0f);
    gemm16_nn<<<dim3(2, 512), thr>>>(x16, wt16, fc0_b, v, nullptr,
                                     512, 512, 512,
                                     nullptr, nullptr, nullptr, nullptr);
    ln_relu<<<NPTS, thr>>>(v, ln0_g, ln0_b, hbuf, a16);

    for (int L = 0; L < 2; L++) {
        const float*  prev   = L ? out : hbuf;
        const __half* prev16 = a16;
        float* lout = out;
        __half* WQT = wt16 + (size_t)(1 + 3 * L) * 524288u;
        __half* WKT = wt16 + (size_t)(2 + 3 * L) * 524288u;
        __half* WVT = wt16 + (size_t)(3 + 3 * L) * 524288u;
        const float* BQ  = bq + (size_t)L * 1024;
        const float* BKb = bk + (size_t)L * 1024;
        const float* BV  = bv + (size_t)L * 1024;

        transpose_h<<<dim3(32, 16), tb>>>(wv + (size_t)L * 524288u, 512, 1024,
                                          WVT, 1.0f);
        // V projection (fp32 out, needed for attn combine)
        gemm16_nn<<<dim3(4, 512), thr>>>(prev16, WVT, BV, v, nullptr,
                                         512, 512, 1024,
                                         nullptr, nullptr, nullptr, nullptr);
        // V^T fp16 for kv gemm
        transpose_h<<<dim3(32, 2048), tb>>>(v, NPTS, 1024, vT16, 1.0f);

        transpose_h<<<dim3(32, 16), tb>>>(wk + (size_t)L * 524288u, 512, 1024,
                                          WKT, 1.0f);
        // K projection: fp16-only output (k16 parked in q16 buffer)
        // (+ ss partials, + colsum partials)
        gemm16_nn<<<dim3(4, 512), thr>>>(prev16, WKT, BKb, nullptr, q16,
                                         512, 512, 1024,
                                         red + 4096, ksp, nullptr, nullptr);
        reduce_to_scalar<<<1, thr>>>(red + 4096, 2048, scal + 1);
        ks_reduce512<<<4, thr>>>(ksp, ks);
        // K^T fp16
        transpose_hh<<<dim3(16, 1024), tb>>>(q16, NPTS, 1024, kT16);

        // kvs = K^T V per head (fp16 split-K, deterministic)
        gemm16_kv<<<dim3(2, 4, 64), thr>>>(kT16, vT16, kvp);
        kv_reduce<<<2048, thr>>>(kvp, kvs);
        transpose_h<<<dim3(16, 16), tb>>>(kvs, 512, 512, kvsT16, 0.00390625f);
        transpose_h<<<dim3(16, 16), tb>>>(kvs + 262144u, 512, 512,
                                          kvsT16 + 262144u, 0.00390625f);

        // Q projection: fp16-only output, overwrites k16 (+ ss, + q.ks)
        transpose_h<<<dim3(32, 16), tb>>>(wq + (size_t)L * 524288u, 512, 1024,
                                          WQT, 1.0f);
        gemm16_nn<<<dim3(4, 512), thr>>>(prev16, WQT, BQ, nullptr, q16,
                                         512, 512, 1024,
                                         red, nullptr, ks, qdp);
        reduce_to_scalar<<<1, thr>>>(red, 2048, scal + 0);
        inv_from_qdp<<<256, thr>>>(qdp, scal, inv);

        // fused Q@kvs + attention combine; attn aliases V's head-0 half
        gemm16_attn<<<dim3(2, 512), thr>>>(q16, kvsT16, v, inv, scal, v, 0);
        gemm16_attn<<<dim3(2, 512), thr>>>(q16 + 512, kvsT16 + 262144u,
                                           v + 512, inv + 1, scal, v, 1);

        // residual + LN (writes prev16 for next layer when L==0)
        combine_res_ln<<<NPTS, thr>>>(v, prev,
                                      lng + (size_t)L * 512, lnb + (size_t)L * 512,
                                      lout, L == 0 ? a16 : nullptr);
    }
}